// round 1
// baseline (speedup 1.0000x reference)
#include <cuda_runtime.h>
#include <math.h>

#define BB   64
#define NN   512
#define FIN  256
#define DD   128
#define KTOP 20
#define HIDN 512

// ---- scratch (no allocations allowed; device globals) ----
static __device__ float d_xl[BB*NN*DD];      // [b,n,d] lin(x)
static __device__ float d_g [BB*NN*DD];      // [b,n,d] gated GCN output
static __device__ float d_o1[BB*DD*HIDN];    // [b,d,h] first linear
static __device__ float d_p [BB*NN];
static __device__ float d_q [BB*NN];
static __device__ float d_rinv[NN];
static __device__ float d_r [NN];
static __device__ float d_s [NN];
static __device__ float d_cosm[NN*NN];
static __device__ int   d_topk[NN*KTOP];

// ---------------------------------------------------------------
// K0: per-node norms (rsqrt) and emb·att_em_i / emb·att_em_j
// ---------------------------------------------------------------
__global__ void k_norm(const float* __restrict__ emb,
                       const float* __restrict__ aei,
                       const float* __restrict__ aej) {
    int n = blockIdx.x, t = threadIdx.x;           // 128 threads
    float w  = emb[n*DD + t];
    float v0 = w*w, v1 = w*aei[t], v2 = w*aej[t];
    #pragma unroll
    for (int o = 16; o; o >>= 1) {
        v0 += __shfl_xor_sync(0xffffffffu, v0, o);
        v1 += __shfl_xor_sync(0xffffffffu, v1, o);
        v2 += __shfl_xor_sync(0xffffffffu, v2, o);
    }
    __shared__ float s0[4], s1[4], s2[4];
    int wid = t >> 5, lane = t & 31;
    if (lane == 0) { s0[wid]=v0; s1[wid]=v1; s2[wid]=v2; }
    __syncthreads();
    if (t == 0) {
        float a = s0[0]+s0[1]+s0[2]+s0[3];
        float b = s1[0]+s1[1]+s1[2]+s1[3];
        float c = s2[0]+s2[1]+s2[2]+s2[3];
        d_rinv[n] = rsqrtf(a);
        d_r[n] = b; d_s[n] = c;
    }
}

// ---------------------------------------------------------------
// K1: cosine matrix (512x512, K=128), 64x64 tiles, 4x4 microtile
// ---------------------------------------------------------------
__global__ void k_cos(const float* __restrict__ emb) {
    __shared__ float sAt[32][68];   // [k][i-row]
    __shared__ float sBt[32][68];   // [k][j-row]
    int i0 = blockIdx.y * 64, j0 = blockIdx.x * 64;
    int tid = threadIdx.x;           // 256
    int tx = tid & 15, ty = tid >> 4;
    float c[4][4] = {};
    for (int k0 = 0; k0 < DD; k0 += 32) {
        #pragma unroll
        for (int a = 0; a < 8; a++) {
            int idx = tid + a*256;
            int row = idx >> 5, kk = idx & 31;
            sAt[kk][row] = emb[(i0+row)*DD + k0 + kk];
            sBt[kk][row] = emb[(j0+row)*DD + k0 + kk];
        }
        __syncthreads();
        #pragma unroll
        for (int kk = 0; kk < 32; kk++) {
            float av[4], bv[4];
            *(float4*)av = *(const float4*)&sAt[kk][ty*4];
            *(float4*)bv = *(const float4*)&sBt[kk][tx*4];
            #pragma unroll
            for (int ii = 0; ii < 4; ii++)
                #pragma unroll
                for (int jj = 0; jj < 4; jj++)
                    c[ii][jj] += av[ii]*bv[jj];
        }
        __syncthreads();
    }
    float rj[4];
    #pragma unroll
    for (int jj = 0; jj < 4; jj++) rj[jj] = d_rinv[j0 + tx*4 + jj];
    #pragma unroll
    for (int ii = 0; ii < 4; ii++) {
        float ri = d_rinv[i0 + ty*4 + ii];
        float4 v;
        v.x = c[ii][0]*ri*rj[0]; v.y = c[ii][1]*ri*rj[1];
        v.z = c[ii][2]*ri*rj[2]; v.w = c[ii][3]*ri*rj[3];
        *(float4*)&d_cosm[(i0 + ty*4 + ii)*NN + j0 + tx*4] = v;
    }
}

// ---------------------------------------------------------------
// K2: top-20 per row, descending, ties -> lower index (jax top_k)
// ---------------------------------------------------------------
__global__ void k_topk() {
    int i = blockIdx.x, tid = threadIdx.x;  // 256 threads
    __shared__ float cv[NN];
    __shared__ float rv[256];
    __shared__ int   ri[256];
    cv[tid]       = d_cosm[i*NN + tid];
    cv[tid + 256] = d_cosm[i*NN + tid + 256];
    __syncthreads();
    for (int t = 0; t < KTOP; t++) {
        float bv = cv[tid]; int bi = tid;
        float v2 = cv[tid + 256];
        if (v2 > bv) { bv = v2; bi = tid + 256; }   // equal -> keep lower idx
        rv[tid] = bv; ri[tid] = bi;
        __syncthreads();
        #pragma unroll
        for (int s2 = 128; s2 > 0; s2 >>= 1) {
            if (tid < s2) {
                float v = rv[tid + s2]; int ii = ri[tid + s2];
                if (v > rv[tid] || (v == rv[tid] && ii < ri[tid])) {
                    rv[tid] = v; ri[tid] = ii;
                }
            }
            __syncthreads();
        }
        if (tid == 0) { d_topk[i*KTOP + t] = ri[0]; cv[ri[0]] = -INFINITY; }
        __syncthreads();
    }
}

// ---------------------------------------------------------------
// K3: xl[b,n,d] = sum_f data[b,f,n] * lin_w[d,f]
//   tile: 128 n x 128 d per block, K-chunks of 32, 8x8 microtile
// ---------------------------------------------------------------
__global__ void __launch_bounds__(256) k_xl(const float* __restrict__ data,
                                            const float* __restrict__ linw) {
    __shared__ float sW[32][DD+4];  // [kk][d]
    __shared__ float sD[32][DD+4];  // [kk][n]
    int b = blockIdx.y, n0 = blockIdx.x * 128;
    int tid = threadIdx.x, tx = tid & 15, ty = tid >> 4;
    float c[8][8] = {};
    for (int f0 = 0; f0 < FIN; f0 += 32) {
        #pragma unroll
        for (int a = 0; a < 16; a++) {
            int idx = tid + a*256;
            int kk = idx & 31, dd = idx >> 5;
            sW[kk][dd] = linw[dd*FIN + f0 + kk];
        }
        #pragma unroll
        for (int a = 0; a < 16; a++) {
            int idx = tid + a*256;
            int nn2 = idx & 127, kk = idx >> 7;
            sD[kk][nn2] = data[(b*FIN + f0 + kk)*NN + n0 + nn2];
        }
        __syncthreads();
        #pragma unroll
        for (int kk = 0; kk < 32; kk++) {
            float nf[8], df[8];
            *(float4*)nf     = *(const float4*)&sD[kk][ty*8];
            *(float4*)(nf+4) = *(const float4*)&sD[kk][ty*8+4];
            *(float4*)df     = *(const float4*)&sW[kk][tx*8];
            *(float4*)(df+4) = *(const float4*)&sW[kk][tx*8+4];
            #pragma unroll
            for (int i = 0; i < 8; i++)
                #pragma unroll
                for (int j = 0; j < 8; j++)
                    c[i][j] += nf[i]*df[j];
        }
        __syncthreads();
    }
    #pragma unroll
    for (int i = 0; i < 8; i++) {
        size_t base = ((size_t)b*NN + n0 + ty*8 + i)*DD + tx*8;
        float4 v0 = {c[i][0], c[i][1], c[i][2], c[i][3]};
        float4 v1 = {c[i][4], c[i][5], c[i][6], c[i][7]};
        *(float4*)&d_xl[base]     = v0;
        *(float4*)&d_xl[base + 4] = v1;
    }
}

// ---------------------------------------------------------------
// K4: p = xl . att_i, q = xl . att_j  (one warp per node)
// ---------------------------------------------------------------
__global__ void k_pq(const float* __restrict__ ai, const float* __restrict__ aj) {
    int w    = (blockIdx.x*blockDim.x + threadIdx.x) >> 5;
    int lane = threadIdx.x & 31;
    const float* xr = d_xl + (size_t)w*DD;
    float pv = 0.f, qv = 0.f;
    #pragma unroll
    for (int j = 0; j < 4; j++) {
        float v = xr[lane + 32*j];
        pv += v*ai[lane + 32*j];
        qv += v*aj[lane + 32*j];
    }
    #pragma unroll
    for (int o = 16; o; o >>= 1) {
        pv += __shfl_xor_sync(0xffffffffu, pv, o);
        qv += __shfl_xor_sync(0xffffffffu, qv, o);
    }
    if (lane == 0) { d_p[w] = pv; d_q[w] = qv; }
}

// ---------------------------------------------------------------
// K5: attention softmax (20 edges/dest) + aggregate + BN + ReLU + emb gate
// ---------------------------------------------------------------
__global__ void k_attn(const float* __restrict__ emb,
                       const float* __restrict__ gbias,
                       const float* __restrict__ gamma,
                       const float* __restrict__ beta) {
    int warp = (blockIdx.x*256 + threadIdx.x) >> 5;   // = b*NN + n
    int lane = threadIdx.x & 31;
    int b = warp >> 9, n = warp & 511;
    int src = 0; float alpha = -1e30f;
    if (lane < KTOP) {
        src = d_topk[n*KTOP + lane];
        alpha = d_p[warp] + d_r[n] + d_q[b*NN + src] + d_s[src];
        alpha = alpha > 0.f ? alpha : 0.2f*alpha;     // leaky_relu(0.2)
    }
    float m = alpha;
    #pragma unroll
    for (int o = 16; o; o >>= 1) m = fmaxf(m, __shfl_xor_sync(0xffffffffu, m, o));
    float ex = (lane < KTOP) ? expf(alpha - m) : 0.f;
    float sm = ex;
    #pragma unroll
    for (int o = 16; o; o >>= 1) sm += __shfl_xor_sync(0xffffffffu, sm, o);
    float aw = ex / sm;

    float acc0 = 0.f, acc1 = 0.f, acc2 = 0.f, acc3 = 0.f;
    #pragma unroll
    for (int k = 0; k < KTOP; k++) {
        int   sk = __shfl_sync(0xffffffffu, src, k);
        float ak = __shfl_sync(0xffffffffu, aw,  k);
        const float* xr = d_xl + ((size_t)b*NN + sk)*DD;
        acc0 += ak*xr[lane];      acc1 += ak*xr[lane + 32];
        acc2 += ak*xr[lane + 64]; acc3 += ak*xr[lane + 96];
    }
    const float inv = rsqrtf(1.0f + 1e-5f);
    float accs[4] = {acc0, acc1, acc2, acc3};
    #pragma unroll
    for (int j = 0; j < 4; j++) {
        int dd = lane + 32*j;
        float h = (accs[j] + gbias[dd])*(gamma[dd]*inv) + beta[dd];
        h = fmaxf(h, 0.f);
        d_g[(size_t)warp*DD + dd] = h * emb[n*DD + dd];
    }
}

// ---------------------------------------------------------------
// K6: o1[b,d,h] = sum_n g[b,n,d] * w1[h,n]     (128d x 128h tiles)
// ---------------------------------------------------------------
__global__ void __launch_bounds__(256) k_gemm1(const float* __restrict__ w1) {
    __shared__ float sA[32][DD+4];  // [kk(n)][d]
    __shared__ float sB[32][DD+4];  // [kk(n)][h]
    int b = blockIdx.y, h0 = blockIdx.x * 128;
    int tid = threadIdx.x, tx = tid & 15, ty = tid >> 4;
    float c[8][8] = {};
    for (int n0 = 0; n0 < NN; n0 += 32) {
        #pragma unroll
        for (int a = 0; a < 16; a++) {
            int idx = tid + a*256;
            int dd = idx & 127, kk = idx >> 7;
            sA[kk][dd] = d_g[((size_t)b*NN + n0 + kk)*DD + dd];
        }
        #pragma unroll
        for (int a = 0; a < 16; a++) {
            int idx = tid + a*256;
            int kk = idx & 31, hh = idx >> 5;
            sB[kk][hh] = w1[(h0 + hh)*NN + n0 + kk];
        }
        __syncthreads();
        #pragma unroll
        for (int kk = 0; kk < 32; kk++) {
            float af[8], bf[8];
            *(float4*)af     = *(const float4*)&sA[kk][ty*8];
            *(float4*)(af+4) = *(const float4*)&sA[kk][ty*8+4];
            *(float4*)bf     = *(const float4*)&sB[kk][tx*8];
            *(float4*)(bf+4) = *(const float4*)&sB[kk][tx*8+4];
            #pragma unroll
            for (int i = 0; i < 8; i++)
                #pragma unroll
                for (int j = 0; j < 8; j++)
                    c[i][j] += af[i]*bf[j];
        }
        __syncthreads();
    }
    #pragma unroll
    for (int i = 0; i < 8; i++) {
        size_t base = ((size_t)b*DD + ty*8 + i)*HIDN + h0 + tx*8;
        float4 v0 = {c[i][0], c[i][1], c[i][2], c[i][3]};
        float4 v1 = {c[i][4], c[i][5], c[i][6], c[i][7]};
        *(float4*)&d_o1[base]     = v0;
        *(float4*)&d_o1[base + 4] = v1;
    }
}

// ---------------------------------------------------------------
// K7: out[b,d,h2] = sigmoid(sum_h o1[b,d,h]*w2[h2,h] + b2[h2])
// ---------------------------------------------------------------
__global__ void __launch_bounds__(256) k_gemm2(const float* __restrict__ w2,
                                               const float* __restrict__ b2,
                                               float* __restrict__ out) {
    __shared__ float sA[32][DD+4];  // [kk(h)][d]
    __shared__ float sB[32][DD+4];  // [kk(h)][h2]
    int b = blockIdx.y, h20 = blockIdx.x * 128;
    int tid = threadIdx.x, tx = tid & 15, ty = tid >> 4;
    float c[8][8] = {};
    for (int hk0 = 0; hk0 < HIDN; hk0 += 32) {
        #pragma unroll
        for (int a = 0; a < 16; a++) {
            int idx = tid + a*256;
            int kk = idx & 31, dd = idx >> 5;
            sA[kk][dd] = d_o1[((size_t)b*DD + dd)*HIDN + hk0 + kk];
        }
        #pragma unroll
        for (int a = 0; a < 16; a++) {
            int idx = tid + a*256;
            int kk = idx & 31, hh = idx >> 5;
            sB[kk][hh] = w2[(h20 + hh)*HIDN + hk0 + kk];
        }
        __syncthreads();
        #pragma unroll
        for (int kk = 0; kk < 32; kk++) {
            float af[8], bf[8];
            *(float4*)af     = *(const float4*)&sA[kk][ty*8];
            *(float4*)(af+4) = *(const float4*)&sA[kk][ty*8+4];
            *(float4*)bf     = *(const float4*)&sB[kk][tx*8];
            *(float4*)(bf+4) = *(const float4*)&sB[kk][tx*8+4];
            #pragma unroll
            for (int i = 0; i < 8; i++)
                #pragma unroll
                for (int j = 0; j < 8; j++)
                    c[i][j] += af[i]*bf[j];
        }
        __syncthreads();
    }
    #pragma unroll
    for (int i = 0; i < 8; i++) {
        size_t base = ((size_t)b*DD + ty*8 + i)*HIDN + h20 + tx*8;
        float v[8];
        #pragma unroll
        for (int j = 0; j < 8; j++) {
            float x = c[i][j] + b2[h20 + tx*8 + j];
            v[j] = 1.0f / (1.0f + expf(-x));
        }
        float4 v0 = {v[0], v[1], v[2], v[3]};
        float4 v1 = {v[4], v[5], v[6], v[7]};
        *(float4*)&out[base]     = v0;
        *(float4*)&out[base + 4] = v1;
    }
}

// ---------------------------------------------------------------
// K8: pack trailing outputs (emb_weight copy, topk_idx as float)
// ---------------------------------------------------------------
__global__ void k_pack(const float* __restrict__ emb, float* __restrict__ out, int mode) {
    int i = blockIdx.x*256 + threadIdx.x;
    const int OUT0 = BB*DD*HIDN;
    if (i < NN*DD) out[OUT0 + i] = emb[i];
    if (mode && i < NN*KTOP) out[OUT0 + NN*DD + i] = (float)d_topk[i];
}

extern "C" void kernel_launch(void* const* d_in, const int* in_sizes, int n_in,
                              void* d_out, int out_size) {
    const float* data  = (const float*)d_in[0];
    const float* emb   = (const float*)d_in[1];
    const float* linw  = (const float*)d_in[2];
    const float* ai    = (const float*)d_in[3];
    const float* aj    = (const float*)d_in[4];
    const float* aei   = (const float*)d_in[5];
    const float* aej   = (const float*)d_in[6];
    const float* gbias = (const float*)d_in[7];
    const float* gamma = (const float*)d_in[8];
    const float* beta  = (const float*)d_in[9];
    const float* w1    = (const float*)d_in[10];
    const float* w2    = (const float*)d_in[11];
    const float* b2    = (const float*)d_in[12];
    float* out = (float*)d_out;

    k_norm<<<NN, 128>>>(emb, aei, aej);
    k_cos <<<dim3(8, 8), 256>>>(emb);
    k_topk<<<NN, 256>>>();
    k_xl  <<<dim3(4, BB), 256>>>(data, linw);
    k_pq  <<<(BB*NN)/8, 256>>>(ai, aj);
    k_attn<<<(BB*NN)/8, 256>>>(emb, gbias, gamma, beta);
    k_gemm1<<<dim3(4, BB), 256>>>(w1);
    k_gemm2<<<dim3(4, BB), 256>>>(w2, b2, out);

    const int OUT0 = BB*DD*HIDN;
    if (out_size >= OUT0 + NN*DD) {
        int mode = (out_size >= OUT0 + NN*DD + NN*KTOP) ? 1 : 0;
        k_pack<<<(NN*DD + 255)/256, 256>>>(emb, out, mode);
    }
}

// round 2
// speedup vs baseline: 2.3030x; 2.3030x over previous
#include <cuda_runtime.h>
#include <math.h>

#define BB   64
#define NN   512
#define FIN  256
#define DD   128
#define KTOP 20
#define HIDN 512

// ---- scratch (no allocations allowed; device globals) ----
static __device__ float d_xl[BB*NN*DD];      // [b,n,d] lin(x)
static __device__ float d_g [BB*NN*DD];      // [b,n,d] gated GCN output
static __device__ float d_o1[BB*DD*HIDN];    // [b,d,h] first linear
static __device__ float d_p [BB*NN];
static __device__ float d_q [BB*NN];
static __device__ float d_rinv[NN];
static __device__ float d_r [NN];
static __device__ float d_s [NN];
static __device__ float d_cosm[NN*NN];
static __device__ int   d_topk[NN*KTOP];

// ---------------- tf32 helpers ----------------
__device__ __forceinline__ unsigned f2tf32(float x) {
    unsigned y; asm("cvt.rna.tf32.f32 %0, %1;" : "=r"(y) : "f"(x)); return y;
}
__device__ __forceinline__ void mma_tf32(float c[4],
        unsigned a0, unsigned a1, unsigned a2, unsigned a3,
        unsigned b0, unsigned b1) {
    asm volatile(
        "mma.sync.aligned.m16n8k8.row.col.f32.tf32.tf32.f32 "
        "{%0,%1,%2,%3}, {%4,%5,%6,%7}, {%8,%9}, {%0,%1,%2,%3};\n"
        : "+f"(c[0]), "+f"(c[1]), "+f"(c[2]), "+f"(c[3])
        : "r"(a0), "r"(a1), "r"(a2), "r"(a3), "r"(b0), "r"(b1));
}

// MMA mainloop shared by all three GEMMs: sA [128][k:34], sB [128][k:34]
#define MMA_CHUNK(sA, sB, cacc, wm, wn, g, t4)                                  \
    _Pragma("unroll")                                                            \
    for (int ks = 0; ks < 4; ks++) {                                             \
        int k8 = ks * 8;                                                         \
        unsigned af[4][4], bf[4][2];                                             \
        _Pragma("unroll")                                                        \
        for (int mi = 0; mi < 4; mi++) {                                         \
            int r = (wm) + mi*16 + (g);                                          \
            af[mi][0] = sA[r    ][k8 + (t4)    ];                                \
            af[mi][1] = sA[r + 8][k8 + (t4)    ];                                \
            af[mi][2] = sA[r    ][k8 + (t4) + 4];                                \
            af[mi][3] = sA[r + 8][k8 + (t4) + 4];                                \
        }                                                                        \
        _Pragma("unroll")                                                        \
        for (int ni = 0; ni < 4; ni++) {                                         \
            int r = (wn) + ni*8 + (g);                                           \
            bf[ni][0] = sB[r][k8 + (t4)    ];                                    \
            bf[ni][1] = sB[r][k8 + (t4) + 4];                                    \
        }                                                                        \
        _Pragma("unroll")                                                        \
        for (int mi = 0; mi < 4; mi++)                                           \
            _Pragma("unroll")                                                    \
            for (int ni = 0; ni < 4; ni++)                                       \
                mma_tf32(cacc[mi][ni], af[mi][0], af[mi][1], af[mi][2],          \
                         af[mi][3], bf[ni][0], bf[ni][1]);                       \
    }

// ---------------------------------------------------------------
// K0: per-node norms (rsqrt) and emb·att_em_i / emb·att_em_j
// ---------------------------------------------------------------
__global__ void k_norm(const float* __restrict__ emb,
                       const float* __restrict__ aei,
                       const float* __restrict__ aej) {
    int n = blockIdx.x, t = threadIdx.x;           // 128 threads
    float w  = emb[n*DD + t];
    float v0 = w*w, v1 = w*aei[t], v2 = w*aej[t];
    #pragma unroll
    for (int o = 16; o; o >>= 1) {
        v0 += __shfl_xor_sync(0xffffffffu, v0, o);
        v1 += __shfl_xor_sync(0xffffffffu, v1, o);
        v2 += __shfl_xor_sync(0xffffffffu, v2, o);
    }
    __shared__ float s0[4], s1[4], s2[4];
    int wid = t >> 5, lane = t & 31;
    if (lane == 0) { s0[wid]=v0; s1[wid]=v1; s2[wid]=v2; }
    __syncthreads();
    if (t == 0) {
        float a = s0[0]+s0[1]+s0[2]+s0[3];
        float b = s1[0]+s1[1]+s1[2]+s1[3];
        float c = s2[0]+s2[1]+s2[2]+s2[3];
        d_rinv[n] = rsqrtf(a);
        d_r[n] = b; d_s[n] = c;
    }
}

// ---------------------------------------------------------------
// K1: cosine matrix (512x512, K=128)
// ---------------------------------------------------------------
__global__ void k_cos(const float* __restrict__ emb) {
    __shared__ float sAt[32][68];
    __shared__ float sBt[32][68];
    int i0 = blockIdx.y * 64, j0 = blockIdx.x * 64;
    int tid = threadIdx.x;
    int tx = tid & 15, ty = tid >> 4;
    float c[4][4] = {};
    for (int k0 = 0; k0 < DD; k0 += 32) {
        #pragma unroll
        for (int a = 0; a < 8; a++) {
            int idx = tid + a*256;
            int row = idx >> 5, kk = idx & 31;
            sAt[kk][row] = emb[(i0+row)*DD + k0 + kk];
            sBt[kk][row] = emb[(j0+row)*DD + k0 + kk];
        }
        __syncthreads();
        #pragma unroll
        for (int kk = 0; kk < 32; kk++) {
            float av[4], bv[4];
            *(float4*)av = *(const float4*)&sAt[kk][ty*4];
            *(float4*)bv = *(const float4*)&sBt[kk][tx*4];
            #pragma unroll
            for (int ii = 0; ii < 4; ii++)
                #pragma unroll
                for (int jj = 0; jj < 4; jj++)
                    c[ii][jj] += av[ii]*bv[jj];
        }
        __syncthreads();
    }
    float rj[4];
    #pragma unroll
    for (int jj = 0; jj < 4; jj++) rj[jj] = d_rinv[j0 + tx*4 + jj];
    #pragma unroll
    for (int ii = 0; ii < 4; ii++) {
        float ri = d_rinv[i0 + ty*4 + ii];
        float4 v;
        v.x = c[ii][0]*ri*rj[0]; v.y = c[ii][1]*ri*rj[1];
        v.z = c[ii][2]*ri*rj[2]; v.w = c[ii][3]*ri*rj[3];
        *(float4*)&d_cosm[(i0 + ty*4 + ii)*NN + j0 + tx*4] = v;
    }
}

// ---------------------------------------------------------------
// K2: top-20 per row, descending, ties -> lower index
// ---------------------------------------------------------------
__global__ void k_topk() {
    int i = blockIdx.x, tid = threadIdx.x;
    __shared__ float cv[NN];
    __shared__ float rv[256];
    __shared__ int   ri[256];
    cv[tid]       = d_cosm[i*NN + tid];
    cv[tid + 256] = d_cosm[i*NN + tid + 256];
    __syncthreads();
    for (int t = 0; t < KTOP; t++) {
        float bv = cv[tid]; int bi = tid;
        float v2 = cv[tid + 256];
        if (v2 > bv) { bv = v2; bi = tid + 256; }
        rv[tid] = bv; ri[tid] = bi;
        __syncthreads();
        #pragma unroll
        for (int s2 = 128; s2 > 0; s2 >>= 1) {
            if (tid < s2) {
                float v = rv[tid + s2]; int ii = ri[tid + s2];
                if (v > rv[tid] || (v == rv[tid] && ii < ri[tid])) {
                    rv[tid] = v; ri[tid] = ii;
                }
            }
            __syncthreads();
        }
        if (tid == 0) { d_topk[i*KTOP + t] = ri[0]; cv[ri[0]] = -INFINITY; }
        __syncthreads();
    }
}

// ---------------------------------------------------------------
// K3 (tf32 MMA): xl[b,n,d] = sum_f data[b,f,n] * lin_w[d,f]
// ---------------------------------------------------------------
__global__ void __launch_bounds__(256, 2) k_xl(const float* __restrict__ data,
                                               const float* __restrict__ linw) {
    __shared__ unsigned sA[128][34];   // [m=n][k=f]
    __shared__ unsigned sB[128][34];   // [n=d][k=f]
    int b = blockIdx.y, n0 = blockIdx.x * 128;
    int tid = threadIdx.x;
    int w = tid >> 5, lane = tid & 31;
    int g = lane >> 2, t4 = lane & 3;
    int wm = (w & 1) * 64, wn = (w >> 1) * 32;
    float c[4][4][4] = {};
    for (int f0 = 0; f0 < FIN; f0 += 32) {
        #pragma unroll
        for (int a = 0; a < 16; a++) {   // A: transpose load, coalesced over n
            int idx = tid + a*256;
            int nn = idx & 127, kk = idx >> 7;
            sA[nn][kk] = f2tf32(data[((size_t)b*FIN + f0 + kk)*NN + n0 + nn]);
        }
        #pragma unroll
        for (int a = 0; a < 16; a++) {   // B: lin_w, coalesced over k
            int idx = tid + a*256;
            int kk = idx & 31, dd = idx >> 5;
            sB[dd][kk] = f2tf32(linw[dd*FIN + f0 + kk]);
        }
        __syncthreads();
        MMA_CHUNK(sA, sB, c, wm, wn, g, t4)
        __syncthreads();
    }
    #pragma unroll
    for (int mi = 0; mi < 4; mi++)
        #pragma unroll
        for (int ni = 0; ni < 4; ni++) {
            int row = n0 + wm + mi*16 + g, col = wn + ni*8 + t4*2;
            float2 v0 = {c[mi][ni][0], c[mi][ni][1]};
            float2 v1 = {c[mi][ni][2], c[mi][ni][3]};
            *(float2*)&d_xl[((size_t)b*NN + row    )*DD + col] = v0;
            *(float2*)&d_xl[((size_t)b*NN + row + 8)*DD + col] = v1;
        }
}

// ---------------------------------------------------------------
// K4: p = xl . att_i, q = xl . att_j  (one warp per node)
// ---------------------------------------------------------------
__global__ void k_pq(const float* __restrict__ ai, const float* __restrict__ aj) {
    int w    = (blockIdx.x*blockDim.x + threadIdx.x) >> 5;
    int lane = threadIdx.x & 31;
    const float* xr = d_xl + (size_t)w*DD;
    float pv = 0.f, qv = 0.f;
    #pragma unroll
    for (int j = 0; j < 4; j++) {
        float v = xr[lane + 32*j];
        pv += v*ai[lane + 32*j];
        qv += v*aj[lane + 32*j];
    }
    #pragma unroll
    for (int o = 16; o; o >>= 1) {
        pv += __shfl_xor_sync(0xffffffffu, pv, o);
        qv += __shfl_xor_sync(0xffffffffu, qv, o);
    }
    if (lane == 0) { d_p[w] = pv; d_q[w] = qv; }
}

// ---------------------------------------------------------------
// K5: attention softmax (20 edges/dest) + aggregate + BN + ReLU + emb gate
// ---------------------------------------------------------------
__global__ void k_attn(const float* __restrict__ emb,
                       const float* __restrict__ gbias,
                       const float* __restrict__ gamma,
                       const float* __restrict__ beta) {
    int warp = (blockIdx.x*256 + threadIdx.x) >> 5;   // = b*NN + n
    int lane = threadIdx.x & 31;
    int b = warp >> 9, n = warp & 511;
    int src = 0; float alpha = -1e30f;
    if (lane < KTOP) {
        src = d_topk[n*KTOP + lane];
        alpha = d_p[warp] + d_r[n] + d_q[b*NN + src] + d_s[src];
        alpha = alpha > 0.f ? alpha : 0.2f*alpha;     // leaky_relu(0.2)
    }
    float m = alpha;
    #pragma unroll
    for (int o = 16; o; o >>= 1) m = fmaxf(m, __shfl_xor_sync(0xffffffffu, m, o));
    float ex = (lane < KTOP) ? expf(alpha - m) : 0.f;
    float sm = ex;
    #pragma unroll
    for (int o = 16; o; o >>= 1) sm += __shfl_xor_sync(0xffffffffu, sm, o);
    float aw = ex / sm;

    float acc0 = 0.f, acc1 = 0.f, acc2 = 0.f, acc3 = 0.f;
    #pragma unroll
    for (int k = 0; k < KTOP; k++) {
        int   sk = __shfl_sync(0xffffffffu, src, k);
        float ak = __shfl_sync(0xffffffffu, aw,  k);
        const float* xr = d_xl + ((size_t)b*NN + sk)*DD;
        acc0 += ak*xr[lane];      acc1 += ak*xr[lane + 32];
        acc2 += ak*xr[lane + 64]; acc3 += ak*xr[lane + 96];
    }
    const float inv = rsqrtf(1.0f + 1e-5f);
    float accs[4] = {acc0, acc1, acc2, acc3};
    #pragma unroll
    for (int j = 0; j < 4; j++) {
        int dd = lane + 32*j;
        float h = (accs[j] + gbias[dd])*(gamma[dd]*inv) + beta[dd];
        h = fmaxf(h, 0.f);
        d_g[(size_t)warp*DD + dd] = h * emb[n*DD + dd];
    }
}

// ---------------------------------------------------------------
// K6 (tf32 MMA): o1[b,d,h] = sum_n g[b,n,d] * w1[h,n]
// ---------------------------------------------------------------
__global__ void __launch_bounds__(256, 2) k_gemm1(const float* __restrict__ w1) {
    __shared__ unsigned sA[128][34];   // [m=d][k=n]
    __shared__ unsigned sB[128][34];   // [n=h][k=n]
    int b = blockIdx.y, h0 = blockIdx.x * 128;
    int tid = threadIdx.x;
    int w = tid >> 5, lane = tid & 31;
    int g = lane >> 2, t4 = lane & 3;
    int wm = (w & 1) * 64, wn = (w >> 1) * 32;
    float c[4][4][4] = {};
    for (int n0 = 0; n0 < NN; n0 += 32) {
        #pragma unroll
        for (int a = 0; a < 16; a++) {   // A: transpose load from g[n][d]
            int idx = tid + a*256;
            int dd = idx & 127, kk = idx >> 7;
            sA[dd][kk] = f2tf32(d_g[((size_t)b*NN + n0 + kk)*DD + dd]);
        }
        #pragma unroll
        for (int a = 0; a < 16; a++) {   // B: w1[h][n]
            int idx = tid + a*256;
            int kk = idx & 31, hh = idx >> 5;
            sB[hh][kk] = f2tf32(w1[(h0 + hh)*NN + n0 + kk]);
        }
        __syncthreads();
        MMA_CHUNK(sA, sB, c, wm, wn, g, t4)
        __syncthreads();
    }
    #pragma unroll
    for (int mi = 0; mi < 4; mi++)
        #pragma unroll
        for (int ni = 0; ni < 4; ni++) {
            int row = wm + mi*16 + g, col = h0 + wn + ni*8 + t4*2;
            float2 v0 = {c[mi][ni][0], c[mi][ni][1]};
            float2 v1 = {c[mi][ni][2], c[mi][ni][3]};
            *(float2*)&d_o1[((size_t)b*DD + row    )*HIDN + col] = v0;
            *(float2*)&d_o1[((size_t)b*DD + row + 8)*HIDN + col] = v1;
        }
}

// ---------------------------------------------------------------
// K7 (tf32 MMA): out[b,d,h2] = sigmoid(sum_h o1[b,d,h]*w2[h2,h] + b2)
// ---------------------------------------------------------------
__global__ void __launch_bounds__(256, 2) k_gemm2(const float* __restrict__ w2,
                                                  const float* __restrict__ b2,
                                                  float* __restrict__ out) {
    __shared__ unsigned sA[128][34];   // [m=d][k=h]
    __shared__ unsigned sB[128][34];   // [n=h2][k=h]
    int b = blockIdx.y, h20 = blockIdx.x * 128;
    int tid = threadIdx.x;
    int w = tid >> 5, lane = tid & 31;
    int g = lane >> 2, t4 = lane & 3;
    int wm = (w & 1) * 64, wn = (w >> 1) * 32;
    float c[4][4][4] = {};
    for (int hk0 = 0; hk0 < HIDN; hk0 += 32) {
        #pragma unroll
        for (int a = 0; a < 16; a++) {   // A: o1[d][h] direct (k contiguous)
            int idx = tid + a*256;
            int kk = idx & 31, dd = idx >> 5;
            sA[dd][kk] = f2tf32(d_o1[((size_t)b*DD + dd)*HIDN + hk0 + kk]);
        }
        #pragma unroll
        for (int a = 0; a < 16; a++) {   // B: w2[h2][h]
            int idx = tid + a*256;
            int kk = idx & 31, hh = idx >> 5;
            sB[hh][kk] = f2tf32(w2[(h20 + hh)*HIDN + hk0 + kk]);
        }
        __syncthreads();
        MMA_CHUNK(sA, sB, c, wm, wn, g, t4)
        __syncthreads();
    }
    #pragma unroll
    for (int mi = 0; mi < 4; mi++)
        #pragma unroll
        for (int ni = 0; ni < 4; ni++) {
            int row = wm + mi*16 + g, col = h20 + wn + ni*8 + t4*2;
            float bb0 = b2[col], bb1 = b2[col + 1];
            float2 v0, v1;
            v0.x = 1.0f/(1.0f + expf(-(c[mi][ni][0] + bb0)));
            v0.y = 1.0f/(1.0f + expf(-(c[mi][ni][1] + bb1)));
            v1.x = 1.0f/(1.0f + expf(-(c[mi][ni][2] + bb0)));
            v1.y = 1.0f/(1.0f + expf(-(c[mi][ni][3] + bb1)));
            *(float2*)&out[((size_t)b*DD + row    )*HIDN + col] = v0;
            *(float2*)&out[((size_t)b*DD + row + 8)*HIDN + col] = v1;
        }
}

// ---------------------------------------------------------------
// K8: pack trailing outputs (emb_weight copy, topk_idx as float)
// ---------------------------------------------------------------
__global__ void k_pack(const float* __restrict__ emb, float* __restrict__ out, int mode) {
    int i = blockIdx.x*256 + threadIdx.x;
    const int OUT0 = BB*DD*HIDN;
    if (i < NN*DD) out[OUT0 + i] = emb[i];
    if (mode && i < NN*KTOP) out[OUT0 + NN*DD + i] = (float)d_topk[i];
}

extern "C" void kernel_launch(void* const* d_in, const int* in_sizes, int n_in,
                              void* d_out, int out_size) {
    const float* data  = (const float*)d_in[0];
    const float* emb   = (const float*)d_in[1];
    const float* linw  = (const float*)d_in[2];
    const float* ai    = (const float*)d_in[3];
    const float* aj    = (const float*)d_in[4];
    const float* aei   = (const float*)d_in[5];
    const float* aej   = (const float*)d_in[6];
    const float* gbias = (const float*)d_in[7];
    const float* gamma = (const float*)d_in[8];
    const float* beta  = (const float*)d_in[9];
    const float* w1    = (const float*)d_in[10];
    const float* w2    = (const float*)d_in[11];
    const float* b2    = (const float*)d_in[12];
    float* out = (float*)d_out;

    k_norm<<<NN, 128>>>(emb, aei, aej);
    k_cos <<<dim3(8, 8), 256>>>(emb);
    k_topk<<<NN, 256>>>();
    k_xl  <<<dim3(4, BB), 256>>>(data, linw);
    k_pq  <<<(BB*NN)/8, 256>>>(ai, aj);
    k_attn<<<(BB*NN)/8, 256>>>(emb, gbias, gamma, beta);
    k_gemm1<<<dim3(4, BB), 256>>>(w1);
    k_gemm2<<<dim3(4, BB), 256>>>(w2, b2, out);

    const int OUT0 = BB*DD*HIDN;
    if (out_size >= OUT0 + NN*DD) {
        int mode = (out_size >= OUT0 + NN*DD + NN*KTOP) ? 1 : 0;
        k_pack<<<(NN*DD + 255)/256, 256>>>(emb, out, mode);
    }
}

// round 3
// speedup vs baseline: 3.4296x; 1.4892x over previous
#include <cuda_runtime.h>
#include <cuda_fp16.h>
#include <math.h>

#define BB   64
#define NN   512
#define FIN  256
#define DD   128
#define KTOP 20
#define HIDN 512

// ---- scratch (no allocations allowed; device globals) ----
static __device__ float  d_xl[BB*NN*DD];      // [b,n,d] lin(x)
static __device__ __half d_xl16[BB*NN*DD];    // fp16 mirror for attn gather
static __device__ float  d_g [BB*NN*DD];      // [b,n,d] gated GCN output
static __device__ float  d_o1[BB*DD*HIDN];    // [b,d,h] first linear
static __device__ float  d_p [BB*NN];
static __device__ float  d_q [BB*NN];
static __device__ float  d_rinv[NN];
static __device__ float  d_r [NN];
static __device__ float  d_s [NN];
static __device__ float  d_cosm[NN*NN];
static __device__ int    d_topk[NN*KTOP];

// ---------------- MMA / cp.async helpers ----------------
__device__ __forceinline__ void mma_tf32(float c[4],
        unsigned a0, unsigned a1, unsigned a2, unsigned a3,
        unsigned b0, unsigned b1) {
    asm volatile(
        "mma.sync.aligned.m16n8k8.row.col.f32.tf32.tf32.f32 "
        "{%0,%1,%2,%3}, {%4,%5,%6,%7}, {%8,%9}, {%0,%1,%2,%3};\n"
        : "+f"(c[0]), "+f"(c[1]), "+f"(c[2]), "+f"(c[3])
        : "r"(a0), "r"(a1), "r"(a2), "r"(a3), "r"(b0), "r"(b1));
}
__device__ __forceinline__ void cpa16(unsigned* dst, const float* src) {
    unsigned ds = (unsigned)__cvta_generic_to_shared(dst);
    asm volatile("cp.async.cg.shared.global [%0], [%1], 16;" :: "r"(ds), "l"(src));
}
#define CP_COMMIT asm volatile("cp.async.commit_group;")
#define CP_WAIT1  asm volatile("cp.async.wait_group 1;")
#define CP_WAIT0  asm volatile("cp.async.wait_group 0;")

// Stage geometry (in 32-bit words):
//  A_kn: [32][136]   = 4352 words   (k-major A: conflict-free, 136 % 32 == 8)
//  A_mk: [128][36]   = 4608 words
//  B   : [128][36]   = 4608 words   (36 % 32 == 4 -> conflict-free frag loads)
#define A_KN_WORDS 4352
#define MK_WORDS   4608
#define STG_KN     (A_KN_WORDS + MK_WORDS)   // 8960 w = 35840 B
#define STG_MK     (2*MK_WORDS)              // 9216 w = 36864 B

// compute one 32-wide K chunk; A in [k][136] layout
#define CHUNK_KN(pA, pB)                                                        \
    _Pragma("unroll")                                                            \
    for (int ks = 0; ks < 4; ks++) {                                             \
        int k8 = ks*8;                                                           \
        unsigned af[4][4], bf[4][2];                                             \
        _Pragma("unroll")                                                        \
        for (int mi = 0; mi < 4; mi++) {                                         \
            int r = wm + mi*16 + g;                                              \
            af[mi][0] = (pA)[(k8+t4  )*136 + r    ];                             \
            af[mi][1] = (pA)[(k8+t4  )*136 + r + 8];                             \
            af[mi][2] = (pA)[(k8+t4+4)*136 + r    ];                             \
            af[mi][3] = (pA)[(k8+t4+4)*136 + r + 8];                             \
        }                                                                        \
        _Pragma("unroll")                                                        \
        for (int ni = 0; ni < 4; ni++) {                                         \
            int rn = wn + ni*8 + g;                                              \
            bf[ni][0] = (pB)[rn*36 + k8+t4    ];                                 \
            bf[ni][1] = (pB)[rn*36 + k8+t4 + 4];                                 \
        }                                                                        \
        _Pragma("unroll")                                                        \
        for (int mi = 0; mi < 4; mi++)                                           \
            _Pragma("unroll")                                                    \
            for (int ni = 0; ni < 4; ni++)                                       \
                mma_tf32(c[mi][ni], af[mi][0], af[mi][1], af[mi][2],             \
                         af[mi][3], bf[ni][0], bf[ni][1]);                       \
    }

// compute one 32-wide K chunk; A in [m][36] layout
#define CHUNK_MK(pA, pB)                                                        \
    _Pragma("unroll")                                                            \
    for (int ks = 0; ks < 4; ks++) {                                             \
        int k8 = ks*8;                                                           \
        unsigned af[4][4], bf[4][2];                                             \
        _Pragma("unroll")                                                        \
        for (int mi = 0; mi < 4; mi++) {                                         \
            int r = wm + mi*16 + g;                                              \
            af[mi][0] = (pA)[(r    )*36 + k8+t4    ];                            \
            af[mi][1] = (pA)[(r + 8)*36 + k8+t4    ];                            \
            af[mi][2] = (pA)[(r    )*36 + k8+t4 + 4];                            \
            af[mi][3] = (pA)[(r + 8)*36 + k8+t4 + 4];                            \
        }                                                                        \
        _Pragma("unroll")                                                        \
        for (int ni = 0; ni < 4; ni++) {                                         \
            int rn = wn + ni*8 + g;                                              \
            bf[ni][0] = (pB)[rn*36 + k8+t4    ];                                 \
            bf[ni][1] = (pB)[rn*36 + k8+t4 + 4];                                 \
        }                                                                        \
        _Pragma("unroll")                                                        \
        for (int mi = 0; mi < 4; mi++)                                           \
            _Pragma("unroll")                                                    \
            for (int ni = 0; ni < 4; ni++)                                       \
                mma_tf32(c[mi][ni], af[mi][0], af[mi][1], af[mi][2],             \
                         af[mi][3], bf[ni][0], bf[ni][1]);                       \
    }

// ---------------------------------------------------------------
// K0: per-node norms (rsqrt) and emb·att_em_i / emb·att_em_j
// ---------------------------------------------------------------
__global__ void k_norm(const float* __restrict__ emb,
                       const float* __restrict__ aei,
                       const float* __restrict__ aej) {
    int n = blockIdx.x, t = threadIdx.x;           // 128 threads
    float w  = emb[n*DD + t];
    float v0 = w*w, v1 = w*aei[t], v2 = w*aej[t];
    #pragma unroll
    for (int o = 16; o; o >>= 1) {
        v0 += __shfl_xor_sync(0xffffffffu, v0, o);
        v1 += __shfl_xor_sync(0xffffffffu, v1, o);
        v2 += __shfl_xor_sync(0xffffffffu, v2, o);
    }
    __shared__ float s0[4], s1[4], s2[4];
    int wid = t >> 5, lane = t & 31;
    if (lane == 0) { s0[wid]=v0; s1[wid]=v1; s2[wid]=v2; }
    __syncthreads();
    if (t == 0) {
        float a = s0[0]+s0[1]+s0[2]+s0[3];
        float b = s1[0]+s1[1]+s1[2]+s1[3];
        float c = s2[0]+s2[1]+s2[2]+s2[3];
        d_rinv[n] = rsqrtf(a);
        d_r[n] = b; d_s[n] = c;
    }
}

// ---------------------------------------------------------------
// K1: cosine matrix (512x512, K=128), fp32 (must not perturb topk)
// ---------------------------------------------------------------
__global__ void k_cos(const float* __restrict__ emb) {
    __shared__ float sAt[32][68];
    __shared__ float sBt[32][68];
    int i0 = blockIdx.y * 64, j0 = blockIdx.x * 64;
    int tid = threadIdx.x;
    int tx = tid & 15, ty = tid >> 4;
    float c[4][4] = {};
    for (int k0 = 0; k0 < DD; k0 += 32) {
        #pragma unroll
        for (int a = 0; a < 8; a++) {
            int idx = tid + a*256;
            int row = idx >> 5, kk = idx & 31;
            sAt[kk][row] = emb[(i0+row)*DD + k0 + kk];
            sBt[kk][row] = emb[(j0+row)*DD + k0 + kk];
        }
        __syncthreads();
        #pragma unroll
        for (int kk = 0; kk < 32; kk++) {
            float av[4], bv[4];
            *(float4*)av = *(const float4*)&sAt[kk][ty*4];
            *(float4*)bv = *(const float4*)&sBt[kk][tx*4];
            #pragma unroll
            for (int ii = 0; ii < 4; ii++)
                #pragma unroll
                for (int jj = 0; jj < 4; jj++)
                    c[ii][jj] += av[ii]*bv[jj];
        }
        __syncthreads();
    }
    float rj[4];
    #pragma unroll
    for (int jj = 0; jj < 4; jj++) rj[jj] = d_rinv[j0 + tx*4 + jj];
    #pragma unroll
    for (int ii = 0; ii < 4; ii++) {
        float ri = d_rinv[i0 + ty*4 + ii];
        float4 v;
        v.x = c[ii][0]*ri*rj[0]; v.y = c[ii][1]*ri*rj[1];
        v.z = c[ii][2]*ri*rj[2]; v.w = c[ii][3]*ri*rj[3];
        *(float4*)&d_cosm[(i0 + ty*4 + ii)*NN + j0 + tx*4] = v;
    }
}

// ---------------------------------------------------------------
// K2: top-20 per row — one WARP per row, all in registers
// ---------------------------------------------------------------
__global__ void k_topk() {
    int warp = (blockIdx.x*256 + threadIdx.x) >> 5;   // row 0..511
    int lane = threadIdx.x & 31;
    float v[16];
    #pragma unroll
    for (int j = 0; j < 16; j++) v[j] = d_cosm[warp*NN + lane + 32*j];
    for (int t = 0; t < KTOP; t++) {
        float bv = v[0]; int bj = 0;
        #pragma unroll
        for (int j = 1; j < 16; j++)
            if (v[j] > bv) { bv = v[j]; bj = j; }   // ties -> lower j -> lower idx
        int bidx = lane + 32*bj;
        #pragma unroll
        for (int o = 16; o; o >>= 1) {
            float ov = __shfl_xor_sync(0xffffffffu, bv, o);
            int   oi = __shfl_xor_sync(0xffffffffu, bidx, o);
            if (ov > bv || (ov == bv && oi < bidx)) { bv = ov; bidx = oi; }
        }
        if (lane == 0) d_topk[warp*KTOP + t] = bidx;
        #pragma unroll
        for (int j = 0; j < 16; j++)
            if (lane + 32*j == bidx) v[j] = -INFINITY;
    }
}

// ---------------------------------------------------------------
// K3 (tf32 MMA, cp.async 2-stage): xl[b,n,d] = sum_f data[b,f,n]*lin_w[d,f]
// ---------------------------------------------------------------
__global__ void __launch_bounds__(256, 2) k_xl(const float* __restrict__ data,
                                               const float* __restrict__ linw) {
    extern __shared__ unsigned smu[];
    int b = blockIdx.y, n0 = blockIdx.x * 128;
    int tid = threadIdx.x;
    int w = tid >> 5, lane = tid & 31;
    int g = lane >> 2, t4 = lane & 3;
    int wm = (w & 1) * 64, wn = (w >> 1) * 32;
    float c[4][4][4] = {};

    // stage s: A at s*STG_KN, B at s*STG_KN + A_KN_WORDS
    #define XL_LOAD(st, f0)                                                      \
        {                                                                        \
            unsigned* pA = smu + (st)*STG_KN;                                    \
            unsigned* pB = pA + A_KN_WORDS;                                      \
            _Pragma("unroll")                                                    \
            for (int a = 0; a < 4; a++) {                                        \
                int idx = tid + a*256;                                           \
                int kk = idx >> 5, n4 = idx & 31;                                \
                cpa16(pA + kk*136 + n4*4,                                        \
                      data + ((size_t)b*FIN + (f0) + kk)*NN + n0 + n4*4);        \
            }                                                                    \
            _Pragma("unroll")                                                    \
            for (int a = 0; a < 4; a++) {                                        \
                int idx = tid + a*256;                                           \
                int dd = idx >> 3, k4 = idx & 7;                                 \
                cpa16(pB + dd*36 + k4*4, linw + dd*FIN + (f0) + k4*4);           \
            }                                                                    \
        }

    XL_LOAD(0, 0)
    CP_COMMIT;
    for (int it = 0; it < FIN/32; it++) {
        if (it + 1 < FIN/32) { XL_LOAD((it+1)&1, (it+1)*32) CP_COMMIT; CP_WAIT1; }
        else                 { CP_WAIT0; }
        __syncthreads();
        unsigned* pA = smu + (it&1)*STG_KN;
        unsigned* pB = pA + A_KN_WORDS;
        CHUNK_KN(pA, pB)
        __syncthreads();
    }
    #undef XL_LOAD
    #pragma unroll
    for (int mi = 0; mi < 4; mi++)
        #pragma unroll
        for (int ni = 0; ni < 4; ni++) {
            int row = n0 + wm + mi*16 + g, col = wn + ni*8 + t4*2;
            float2 v0 = {c[mi][ni][0], c[mi][ni][1]};
            float2 v1 = {c[mi][ni][2], c[mi][ni][3]};
            size_t i0 = ((size_t)b*NN + row    )*DD + col;
            size_t i1 = ((size_t)b*NN + row + 8)*DD + col;
            *(float2*)&d_xl[i0] = v0;
            *(float2*)&d_xl[i1] = v1;
            *(__half2*)&d_xl16[i0] = __floats2half2_rn(v0.x, v0.y);
            *(__half2*)&d_xl16[i1] = __floats2half2_rn(v1.x, v1.y);
        }
}

// ---------------------------------------------------------------
// K4: p = xl . att_i, q = xl . att_j  (one warp per node)
// ---------------------------------------------------------------
__global__ void k_pq(const float* __restrict__ ai, const float* __restrict__ aj) {
    int w    = (blockIdx.x*blockDim.x + threadIdx.x) >> 5;
    int lane = threadIdx.x & 31;
    const float* xr = d_xl + (size_t)w*DD;
    float pv = 0.f, qv = 0.f;
    #pragma unroll
    for (int j = 0; j < 4; j++) {
        float v = xr[lane + 32*j];
        pv += v*ai[lane + 32*j];
        qv += v*aj[lane + 32*j];
    }
    #pragma unroll
    for (int o = 16; o; o >>= 1) {
        pv += __shfl_xor_sync(0xffffffffu, pv, o);
        qv += __shfl_xor_sync(0xffffffffu, qv, o);
    }
    if (lane == 0) { d_p[w] = pv; d_q[w] = qv; }
}

// ---------------------------------------------------------------
// K5: attention softmax + aggregate (fp16 gather) + BN + ReLU + emb gate
// ---------------------------------------------------------------
__global__ void k_attn(const float* __restrict__ emb,
                       const float* __restrict__ gbias,
                       const float* __restrict__ gamma,
                       const float* __restrict__ beta) {
    int warp = (blockIdx.x*256 + threadIdx.x) >> 5;   // = b*NN + n
    int lane = threadIdx.x & 31;
    int b = warp >> 9, n = warp & 511;
    int src = 0; float alpha = -1e30f;
    if (lane < KTOP) {
        src = d_topk[n*KTOP + lane];
        alpha = d_p[warp] + d_r[n] + d_q[b*NN + src] + d_s[src];
        alpha = alpha > 0.f ? alpha : 0.2f*alpha;     // leaky_relu(0.2)
    }
    float m = alpha;
    #pragma unroll
    for (int o = 16; o; o >>= 1) m = fmaxf(m, __shfl_xor_sync(0xffffffffu, m, o));
    float ex = (lane < KTOP) ? expf(alpha - m) : 0.f;
    float sm = ex;
    #pragma unroll
    for (int o = 16; o; o >>= 1) sm += __shfl_xor_sync(0xffffffffu, sm, o);
    float aw = ex / sm;

    float2 acc0 = {0.f,0.f}, acc1 = {0.f,0.f};
    #pragma unroll
    for (int k = 0; k < KTOP; k++) {
        int   sk = __shfl_sync(0xffffffffu, src, k);
        float ak = __shfl_sync(0xffffffffu, aw,  k);
        const __half2* xr = (const __half2*)(d_xl16 + ((size_t)b*NN + sk)*DD);
        float2 f0 = __half22float2(xr[lane]);
        float2 f1 = __half22float2(xr[lane + 32]);
        acc0.x += ak*f0.x; acc0.y += ak*f0.y;
        acc1.x += ak*f1.x; acc1.y += ak*f1.y;
    }
    const float inv = rsqrtf(1.0f + 1e-5f);
    int d0 = 2*lane, d1 = 2*lane + 64;
    float2 gb0 = *(const float2*)&gbias[d0], gb1 = *(const float2*)&gbias[d1];
    float2 gm0 = *(const float2*)&gamma[d0], gm1 = *(const float2*)&gamma[d1];
    float2 bt0 = *(const float2*)&beta [d0], bt1 = *(const float2*)&beta [d1];
    float2 em0 = *(const float2*)&emb[n*DD + d0], em1 = *(const float2*)&emb[n*DD + d1];
    float2 o0, o1;
    o0.x = fmaxf((acc0.x + gb0.x)*(gm0.x*inv) + bt0.x, 0.f) * em0.x;
    o0.y = fmaxf((acc0.y + gb0.y)*(gm0.y*inv) + bt0.y, 0.f) * em0.y;
    o1.x = fmaxf((acc1.x + gb1.x)*(gm1.x*inv) + bt1.x, 0.f) * em1.x;
    o1.y = fmaxf((acc1.y + gb1.y)*(gm1.y*inv) + bt1.y, 0.f) * em1.y;
    *(float2*)&d_g[(size_t)warp*DD + d0] = o0;
    *(float2*)&d_g[(size_t)warp*DD + d1] = o1;
}

// ---------------------------------------------------------------
// K6 (tf32 MMA, cp.async 2-stage): o1[b,d,h] = sum_n g[b,n,d]*w1[h,n]
// ---------------------------------------------------------------
__global__ void __launch_bounds__(256, 2) k_gemm1(const float* __restrict__ w1) {
    extern __shared__ unsigned smu[];
    int b = blockIdx.y, h0 = blockIdx.x * 128;
    int tid = threadIdx.x;
    int w = tid >> 5, lane = tid & 31;
    int g = lane >> 2, t4 = lane & 3;
    int wm = (w & 1) * 64, wn = (w >> 1) * 32;
    float c[4][4][4] = {};

    #define G1_LOAD(st, n0)                                                      \
        {                                                                        \
            unsigned* pA = smu + (st)*STG_KN;                                    \
            unsigned* pB = pA + A_KN_WORDS;                                      \
            _Pragma("unroll")                                                    \
            for (int a = 0; a < 4; a++) {                                        \
                int idx = tid + a*256;                                           \
                int kk = idx >> 5, d4 = idx & 31;                                \
                cpa16(pA + kk*136 + d4*4,                                        \
                      d_g + ((size_t)b*NN + (n0) + kk)*DD + d4*4);               \
            }                                                                    \
            _Pragma("unroll")                                                    \
            for (int a = 0; a < 4; a++) {                                        \
                int idx = tid + a*256;                                           \
                int hh = idx >> 3, k4 = idx & 7;                                 \
                cpa16(pB + hh*36 + k4*4, w1 + (h0 + hh)*NN + (n0) + k4*4);       \
            }                                                                    \
        }

    G1_LOAD(0, 0)
    CP_COMMIT;
    for (int it = 0; it < NN/32; it++) {
        if (it + 1 < NN/32) { G1_LOAD((it+1)&1, (it+1)*32) CP_COMMIT; CP_WAIT1; }
        else                { CP_WAIT0; }
        __syncthreads();
        unsigned* pA = smu + (it&1)*STG_KN;
        unsigned* pB = pA + A_KN_WORDS;
        CHUNK_KN(pA, pB)
        __syncthreads();
    }
    #undef G1_LOAD
    #pragma unroll
    for (int mi = 0; mi < 4; mi++)
        #pragma unroll
        for (int ni = 0; ni < 4; ni++) {
            int row = wm + mi*16 + g, col = h0 + wn + ni*8 + t4*2;
            float2 v0 = {c[mi][ni][0], c[mi][ni][1]};
            float2 v1 = {c[mi][ni][2], c[mi][ni][3]};
            *(float2*)&d_o1[((size_t)b*DD + row    )*HIDN + col] = v0;
            *(float2*)&d_o1[((size_t)b*DD + row + 8)*HIDN + col] = v1;
        }
}

// ---------------------------------------------------------------
// K7 (tf32 MMA, cp.async 2-stage): out = sigmoid(o1 @ w2^T + b2)
// ---------------------------------------------------------------
__global__ void __launch_bounds__(256, 2) k_gemm2(const float* __restrict__ w2,
                                                  const float* __restrict__ b2,
                                                  float* __restrict__ out) {
    extern __shared__ unsigned smu[];
    int b = blockIdx.y, h20 = blockIdx.x * 128;
    int tid = threadIdx.x;
    int w = tid >> 5, lane = tid & 31;
    int g = lane >> 2, t4 = lane & 3;
    int wm = (w & 1) * 64, wn = (w >> 1) * 32;
    float c[4][4][4] = {};

    #define G2_LOAD(st, hk0)                                                     \
        {                                                                        \
            unsigned* pA = smu + (st)*STG_MK;                                    \
            unsigned* pB = pA + MK_WORDS;                                        \
            _Pragma("unroll")                                                    \
            for (int a = 0; a < 4; a++) {                                        \
                int idx = tid + a*256;                                           \
                int dd = idx >> 3, k4 = idx & 7;                                 \
                cpa16(pA + dd*36 + k4*4,                                         \
                      d_o1 + ((size_t)b*DD + dd)*HIDN + (hk0) + k4*4);           \
            }                                                                    \
            _Pragma("unroll")                                                    \
            for (int a = 0; a < 4; a++) {                                        \
                int idx = tid + a*256;                                           \
                int hh = idx >> 3, k4 = idx & 7;                                 \
                cpa16(pB + hh*36 + k4*4, w2 + (h20 + hh)*HIDN + (hk0) + k4*4);   \
            }                                                                    \
        }

    G2_LOAD(0, 0)
    CP_COMMIT;
    for (int it = 0; it < HIDN/32; it++) {
        if (it + 1 < HIDN/32) { G2_LOAD((it+1)&1, (it+1)*32) CP_COMMIT; CP_WAIT1; }
        else                  { CP_WAIT0; }
        __syncthreads();
        unsigned* pA = smu + (it&1)*STG_MK;
        unsigned* pB = pA + MK_WORDS;
        CHUNK_MK(pA, pB)
        __syncthreads();
    }
    #undef G2_LOAD
    #pragma unroll
    for (int mi = 0; mi < 4; mi++)
        #pragma unroll
        for (int ni = 0; ni < 4; ni++) {
            int row = wm + mi*16 + g, col = h20 + wn + ni*8 + t4*2;
            float bb0 = b2[col], bb1 = b2[col + 1];
            float2 v0, v1;
            v0.x = 1.0f/(1.0f + expf(-(c[mi][ni][0] + bb0)));
            v0.y = 1.0f/(1.0f + expf(-(c[mi][ni][1] + bb1)));
            v1.x = 1.0f/(1.0f + expf(-(c[mi][ni][2] + bb0)));
            v1.y = 1.0f/(1.0f + expf(-(c[mi][ni][3] + bb1)));
            *(float2*)&out[((size_t)b*DD + row    )*HIDN + col] = v0;
            *(float2*)&out[((size_t)b*DD + row + 8)*HIDN + col] = v1;
        }
}

// ---------------------------------------------------------------
// K8: pack trailing outputs (emb_weight copy, topk_idx as float)
// ---------------------------------------------------------------
__global__ void k_pack(const float* __restrict__ emb, float* __restrict__ out, int mode) {
    int i = blockIdx.x*256 + threadIdx.x;
    const int OUT0 = BB*DD*HIDN;
    if (i < NN*DD) out[OUT0 + i] = emb[i];
    if (mode && i < NN*KTOP) out[OUT0 + NN*DD + i] = (float)d_topk[i];
}

extern "C" void kernel_launch(void* const* d_in, const int* in_sizes, int n_in,
                              void* d_out, int out_size) {
    const float* data  = (const float*)d_in[0];
    const float* emb   = (const float*)d_in[1];
    const float* linw  = (const float*)d_in[2];
    const float* ai    = (const float*)d_in[3];
    const float* aj    = (const float*)d_in[4];
    const float* aei   = (const float*)d_in[5];
    const float* aej   = (const float*)d_in[6];
    const float* gbias = (const float*)d_in[7];
    const float* gamma = (const float*)d_in[8];
    const float* beta  = (const float*)d_in[9];
    const float* w1    = (const float*)d_in[10];
    const float* w2    = (const float*)d_in[11];
    const float* b2    = (const float*)d_in[12];
    float* out = (float*)d_out;

    const int smem_kn = 2*STG_KN*4;   // 71680 B
    const int smem_mk = 2*STG_MK*4;   // 73728 B
    cudaFuncSetAttribute(k_xl,    cudaFuncAttributeMaxDynamicSharedMemorySize, smem_kn);
    cudaFuncSetAttribute(k_gemm1, cudaFuncAttributeMaxDynamicSharedMemorySize, smem_kn);
    cudaFuncSetAttribute(k_gemm2, cudaFuncAttributeMaxDynamicSharedMemorySize, smem_mk);

    k_norm<<<NN, 128>>>(emb, aei, aej);
    k_cos <<<dim3(8, 8), 256>>>(emb);
    k_topk<<<NN/8, 256>>>();
    k_xl  <<<dim3(4, BB), 256, smem_kn>>>(data, linw);
    k_pq  <<<(BB*NN)/8, 256>>>(ai, aj);
    k_attn<<<(BB*NN)/8, 256>>>(emb, gbias, gamma, beta);
    k_gemm1<<<dim3(4, BB), 256, smem_kn>>>(w1);
    k_gemm2<<<dim3(4, BB), 256, smem_mk>>>(w2, b2, out);

    const int OUT0 = BB*DD*HIDN;
    if (out_size >= OUT0 + NN*DD) {
        int mode = (out_size >= OUT0 + NN*DD + NN*KTOP) ? 1 : 0;
        k_pack<<<(NN*DD + 255)/256, 256>>>(emb, out, mode);
    }
}

// round 4
// speedup vs baseline: 3.6271x; 1.0576x over previous
#include <cuda_runtime.h>
#include <cuda_fp16.h>
#include <math.h>

#define BB   64
#define NN   512
#define FIN  256
#define DD   128
#define KTOP 20
#define HIDN 512

// ---- scratch (no allocations allowed; device globals) ----
static __device__ float  d_xl[BB*NN*DD];      // [b,n,d] lin(x)
static __device__ __half d_xl16[BB*NN*DD];    // fp16 mirror for attn gather
static __device__ float  d_g [BB*NN*DD];      // [b,n,d] gated GCN output
static __device__ float  d_o1[BB*DD*HIDN];    // [b,d,h] first linear
static __device__ float  d_p [BB*NN];
static __device__ float  d_q [BB*NN];
static __device__ float  d_rinv[NN];
static __device__ float  d_r [NN];
static __device__ float  d_s [NN];
static __device__ float  d_cosm[NN*NN];
static __device__ int    d_topk[NN*KTOP];

// ---------------- MMA / cp.async helpers ----------------
__device__ __forceinline__ void mma_tf32(float c[4],
        unsigned a0, unsigned a1, unsigned a2, unsigned a3,
        unsigned b0, unsigned b1) {
    asm volatile(
        "mma.sync.aligned.m16n8k8.row.col.f32.tf32.tf32.f32 "
        "{%0,%1,%2,%3}, {%4,%5,%6,%7}, {%8,%9}, {%0,%1,%2,%3};\n"
        : "+f"(c[0]), "+f"(c[1]), "+f"(c[2]), "+f"(c[3])
        : "r"(a0), "r"(a1), "r"(a2), "r"(a3), "r"(b0), "r"(b1));
}
__device__ __forceinline__ void cpa16(unsigned* dst, const float* src) {
    unsigned ds = (unsigned)__cvta_generic_to_shared(dst);
    asm volatile("cp.async.cg.shared.global [%0], [%1], 16;" :: "r"(ds), "l"(src));
}
#define CP_COMMIT asm volatile("cp.async.commit_group;")
#define CP_WAIT1  asm volatile("cp.async.wait_group 1;")

// Stage geometry (in 32-bit words):
//  A_kn: [32][136]   (k-major A: conflict-free, 136 % 32 == 8)
//  A_mk: [128][36]
//  B   : [128][36]   (36 % 32 == 4 -> conflict-free frag loads)
#define A_KN_WORDS 4352
#define MK_WORDS   4608
#define STG_KN     (A_KN_WORDS + MK_WORDS)   // 8960 w = 35840 B
#define STG_MK     (2*MK_WORDS)              // 9216 w = 36864 B
#define NSTAGE     3

// compute one 32-wide K chunk; A in [k][136] layout
#define CHUNK_KN(pA, pB)                                                        \
    _Pragma("unroll")                                                            \
    for (int ks = 0; ks < 4; ks++) {                                             \
        int k8 = ks*8;                                                           \
        unsigned af[4][4], bf[4][2];                                             \
        _Pragma("unroll")                                                        \
        for (int mi = 0; mi < 4; mi++) {                                         \
            int r = wm + mi*16 + g;                                              \
            af[mi][0] = (pA)[(k8+t4  )*136 + r    ];                             \
            af[mi][1] = (pA)[(k8+t4  )*136 + r + 8];                             \
            af[mi][2] = (pA)[(k8+t4+4)*136 + r    ];                             \
            af[mi][3] = (pA)[(k8+t4+4)*136 + r + 8];                             \
        }                                                                        \
        _Pragma("unroll")                                                        \
        for (int ni = 0; ni < 4; ni++) {                                         \
            int rn = wn + ni*8 + g;                                              \
            bf[ni][0] = (pB)[rn*36 + k8+t4    ];                                 \
            bf[ni][1] = (pB)[rn*36 + k8+t4 + 4];                                 \
        }                                                                        \
        _Pragma("unroll")                                                        \
        for (int mi = 0; mi < 4; mi++)                                           \
            _Pragma("unroll")                                                    \
            for (int ni = 0; ni < 4; ni++)                                       \
                mma_tf32(c[mi][ni], af[mi][0], af[mi][1], af[mi][2],             \
                         af[mi][3], bf[ni][0], bf[ni][1]);                       \
    }

// compute one 32-wide K chunk; A in [m][36] layout
#define CHUNK_MK(pA, pB)                                                        \
    _Pragma("unroll")                                                            \
    for (int ks = 0; ks < 4; ks++) {                                             \
        int k8 = ks*8;                                                           \
        unsigned af[4][4], bf[4][2];                                             \
        _Pragma("unroll")                                                        \
        for (int mi = 0; mi < 4; mi++) {                                         \
            int r = wm + mi*16 + g;                                              \
            af[mi][0] = (pA)[(r    )*36 + k8+t4    ];                            \
            af[mi][1] = (pA)[(r + 8)*36 + k8+t4    ];                            \
            af[mi][2] = (pA)[(r    )*36 + k8+t4 + 4];                            \
            af[mi][3] = (pA)[(r + 8)*36 + k8+t4 + 4];                            \
        }                                                                        \
        _Pragma("unroll")                                                        \
        for (int ni = 0; ni < 4; ni++) {                                         \
            int rn = wn + ni*8 + g;                                              \
            bf[ni][0] = (pB)[rn*36 + k8+t4    ];                                 \
            bf[ni][1] = (pB)[rn*36 + k8+t4 + 4];                                 \
        }                                                                        \
        _Pragma("unroll")                                                        \
        for (int mi = 0; mi < 4; mi++)                                           \
            _Pragma("unroll")                                                    \
            for (int ni = 0; ni < 4; ni++)                                       \
                mma_tf32(c[mi][ni], af[mi][0], af[mi][1], af[mi][2],             \
                         af[mi][3], bf[ni][0], bf[ni][1]);                       \
    }

// ---------------------------------------------------------------
// K0: per-node norms (rsqrt) and emb·att_em_i / emb·att_em_j
// ---------------------------------------------------------------
__global__ void k_norm(const float* __restrict__ emb,
                       const float* __restrict__ aei,
                       const float* __restrict__ aej) {
    int n = blockIdx.x, t = threadIdx.x;           // 128 threads
    float w  = emb[n*DD + t];
    float v0 = w*w, v1 = w*aei[t], v2 = w*aej[t];
    #pragma unroll
    for (int o = 16; o; o >>= 1) {
        v0 += __shfl_xor_sync(0xffffffffu, v0, o);
        v1 += __shfl_xor_sync(0xffffffffu, v1, o);
        v2 += __shfl_xor_sync(0xffffffffu, v2, o);
    }
    __shared__ float s0[4], s1[4], s2[4];
    int wid = t >> 5, lane = t & 31;
    if (lane == 0) { s0[wid]=v0; s1[wid]=v1; s2[wid]=v2; }
    __syncthreads();
    if (t == 0) {
        float a = s0[0]+s0[1]+s0[2]+s0[3];
        float b = s1[0]+s1[1]+s1[2]+s1[3];
        float c = s2[0]+s2[1]+s2[2]+s2[3];
        d_rinv[n] = rsqrtf(a);
        d_r[n] = b; d_s[n] = c;
    }
}

// ---------------------------------------------------------------
// K1: cosine matrix (512x512, K=128), fp32 (must not perturb topk)
// ---------------------------------------------------------------
__global__ void k_cos(const float* __restrict__ emb) {
    __shared__ float sAt[32][68];
    __shared__ float sBt[32][68];
    int i0 = blockIdx.y * 64, j0 = blockIdx.x * 64;
    int tid = threadIdx.x;
    int tx = tid & 15, ty = tid >> 4;
    float c[4][4] = {};
    for (int k0 = 0; k0 < DD; k0 += 32) {
        #pragma unroll
        for (int a = 0; a < 8; a++) {
            int idx = tid + a*256;
            int row = idx >> 5, kk = idx & 31;
            sAt[kk][row] = emb[(i0+row)*DD + k0 + kk];
            sBt[kk][row] = emb[(j0+row)*DD + k0 + kk];
        }
        __syncthreads();
        #pragma unroll
        for (int kk = 0; kk < 32; kk++) {
            float av[4], bv[4];
            *(float4*)av = *(const float4*)&sAt[kk][ty*4];
            *(float4*)bv = *(const float4*)&sBt[kk][tx*4];
            #pragma unroll
            for (int ii = 0; ii < 4; ii++)
                #pragma unroll
                for (int jj = 0; jj < 4; jj++)
                    c[ii][jj] += av[ii]*bv[jj];
        }
        __syncthreads();
    }
    float rj[4];
    #pragma unroll
    for (int jj = 0; jj < 4; jj++) rj[jj] = d_rinv[j0 + tx*4 + jj];
    #pragma unroll
    for (int ii = 0; ii < 4; ii++) {
        float ri = d_rinv[i0 + ty*4 + ii];
        float4 v;
        v.x = c[ii][0]*ri*rj[0]; v.y = c[ii][1]*ri*rj[1];
        v.z = c[ii][2]*ri*rj[2]; v.w = c[ii][3]*ri*rj[3];
        *(float4*)&d_cosm[(i0 + ty*4 + ii)*NN + j0 + tx*4] = v;
    }
}

// ---------------------------------------------------------------
// K2: top-20 per row — one WARP per row, all in registers
// ---------------------------------------------------------------
__global__ void k_topk() {
    int warp = (blockIdx.x*256 + threadIdx.x) >> 5;   // row 0..511
    int lane = threadIdx.x & 31;
    float v[16];
    #pragma unroll
    for (int j = 0; j < 16; j++) v[j] = d_cosm[warp*NN + lane + 32*j];
    for (int t = 0; t < KTOP; t++) {
        float bv = v[0]; int bj = 0;
        #pragma unroll
        for (int j = 1; j < 16; j++)
            if (v[j] > bv) { bv = v[j]; bj = j; }   // ties -> lower j -> lower idx
        int bidx = lane + 32*bj;
        #pragma unroll
        for (int o = 16; o; o >>= 1) {
            float ov = __shfl_xor_sync(0xffffffffu, bv, o);
            int   oi = __shfl_xor_sync(0xffffffffu, bidx, o);
            if (ov > bv || (ov == bv && oi < bidx)) { bv = ov; bidx = oi; }
        }
        if (lane == 0) d_topk[warp*KTOP + t] = bidx;
        #pragma unroll
        for (int j = 0; j < 16; j++)
            if (lane + 32*j == bidx) v[j] = -INFINITY;
    }
}

// ---------------------------------------------------------------
// K3 (tf32 MMA, cp.async 3-stage, 1 sync/iter):
//   xl[b,n,d] = sum_f data[b,f,n] * lin_w[d,f]
// ---------------------------------------------------------------
__global__ void __launch_bounds__(256, 2) k_xl(const float* __restrict__ data,
                                               const float* __restrict__ linw) {
    extern __shared__ unsigned smu[];
    int b = blockIdx.y, n0 = blockIdx.x * 128;
    int tid = threadIdx.x;
    int w = tid >> 5, lane = tid & 31;
    int g = lane >> 2, t4 = lane & 3;
    int wm = (w & 1) * 64, wn = (w >> 1) * 32;
    float c[4][4][4] = {};

    #define XL_LOAD(st, f0)                                                      \
        {                                                                        \
            unsigned* pA = smu + (st)*STG_KN;                                    \
            unsigned* pB = pA + A_KN_WORDS;                                      \
            _Pragma("unroll")                                                    \
            for (int a = 0; a < 4; a++) {                                        \
                int idx = tid + a*256;                                           \
                int kk = idx >> 5, n4 = idx & 31;                                \
                cpa16(pA + kk*136 + n4*4,                                        \
                      data + ((size_t)b*FIN + (f0) + kk)*NN + n0 + n4*4);        \
            }                                                                    \
            _Pragma("unroll")                                                    \
            for (int a = 0; a < 4; a++) {                                        \
                int idx = tid + a*256;                                           \
                int dd = idx >> 3, k4 = idx & 7;                                 \
                cpa16(pB + dd*36 + k4*4, linw + dd*FIN + (f0) + k4*4);           \
            }                                                                    \
        }

    XL_LOAD(0, 0) CP_COMMIT;
    XL_LOAD(1, 32) CP_COMMIT;
    #pragma unroll 1
    for (int it = 0; it < FIN/32; it++) {
        CP_WAIT1;
        __syncthreads();
        if (it + 2 < FIN/32) { XL_LOAD((it+2)%NSTAGE, (it+2)*32) CP_COMMIT; }
        unsigned* pA = smu + (it%NSTAGE)*STG_KN;
        unsigned* pB = pA + A_KN_WORDS;
        CHUNK_KN(pA, pB)
    }
    #undef XL_LOAD
    #pragma unroll
    for (int mi = 0; mi < 4; mi++)
        #pragma unroll
        for (int ni = 0; ni < 4; ni++) {
            int row = n0 + wm + mi*16 + g, col = wn + ni*8 + t4*2;
            float2 v0 = {c[mi][ni][0], c[mi][ni][1]};
            float2 v1 = {c[mi][ni][2], c[mi][ni][3]};
            size_t i0 = ((size_t)b*NN + row    )*DD + col;
            size_t i1 = ((size_t)b*NN + row + 8)*DD + col;
            *(float2*)&d_xl[i0] = v0;
            *(float2*)&d_xl[i1] = v1;
            *(__half2*)&d_xl16[i0] = __floats2half2_rn(v0.x, v0.y);
            *(__half2*)&d_xl16[i1] = __floats2half2_rn(v1.x, v1.y);
        }
}

// ---------------------------------------------------------------
// K4: p = xl . att_i, q = xl . att_j  (one warp per node)
// ---------------------------------------------------------------
__global__ void k_pq(const float* __restrict__ ai, const float* __restrict__ aj) {
    int w    = (blockIdx.x*blockDim.x + threadIdx.x) >> 5;
    int lane = threadIdx.x & 31;
    const float* xr = d_xl + (size_t)w*DD;
    float pv = 0.f, qv = 0.f;
    #pragma unroll
    for (int j = 0; j < 4; j++) {
        float v = xr[lane + 32*j];
        pv += v*ai[lane + 32*j];
        qv += v*aj[lane + 32*j];
    }
    #pragma unroll
    for (int o = 16; o; o >>= 1) {
        pv += __shfl_xor_sync(0xffffffffu, pv, o);
        qv += __shfl_xor_sync(0xffffffffu, qv, o);
    }
    if (lane == 0) { d_p[w] = pv; d_q[w] = qv; }
}

// ---------------------------------------------------------------
// K5: attention softmax + aggregate (fp16 gather) + BN + ReLU + emb gate
// ---------------------------------------------------------------
__global__ void k_attn(const float* __restrict__ emb,
                       const float* __restrict__ gbias,
                       const float* __restrict__ gamma,
                       const float* __restrict__ beta) {
    int warp = (blockIdx.x*256 + threadIdx.x) >> 5;   // = b*NN + n
    int lane = threadIdx.x & 31;
    int b = warp >> 9, n = warp & 511;
    int src = 0; float alpha = -1e30f;
    if (lane < KTOP) {
        src = d_topk[n*KTOP + lane];
        alpha = d_p[warp] + d_r[n] + d_q[b*NN + src] + d_s[src];
        alpha = alpha > 0.f ? alpha : 0.2f*alpha;     // leaky_relu(0.2)
    }
    float m = alpha;
    #pragma unroll
    for (int o = 16; o; o >>= 1) m = fmaxf(m, __shfl_xor_sync(0xffffffffu, m, o));
    float ex = (lane < KTOP) ? expf(alpha - m) : 0.f;
    float sm = ex;
    #pragma unroll
    for (int o = 16; o; o >>= 1) sm += __shfl_xor_sync(0xffffffffu, sm, o);
    float aw = ex / sm;

    float2 acc0 = {0.f,0.f}, acc1 = {0.f,0.f};
    #pragma unroll
    for (int k = 0; k < KTOP; k++) {
        int   sk = __shfl_sync(0xffffffffu, src, k);
        float ak = __shfl_sync(0xffffffffu, aw,  k);
        const __half2* xr = (const __half2*)(d_xl16 + ((size_t)b*NN + sk)*DD);
        float2 f0 = __half22float2(xr[lane]);
        float2 f1 = __half22float2(xr[lane + 32]);
        acc0.x += ak*f0.x; acc0.y += ak*f0.y;
        acc1.x += ak*f1.x; acc1.y += ak*f1.y;
    }
    const float inv = rsqrtf(1.0f + 1e-5f);
    int d0 = 2*lane, d1 = 2*lane + 64;
    float2 gb0 = *(const float2*)&gbias[d0], gb1 = *(const float2*)&gbias[d1];
    float2 gm0 = *(const float2*)&gamma[d0], gm1 = *(const float2*)&gamma[d1];
    float2 bt0 = *(const float2*)&beta [d0], bt1 = *(const float2*)&beta [d1];
    float2 em0 = *(const float2*)&emb[n*DD + d0], em1 = *(const float2*)&emb[n*DD + d1];
    float2 o0, o1;
    o0.x = fmaxf((acc0.x + gb0.x)*(gm0.x*inv) + bt0.x, 0.f) * em0.x;
    o0.y = fmaxf((acc0.y + gb0.y)*(gm0.y*inv) + bt0.y, 0.f) * em0.y;
    o1.x = fmaxf((acc1.x + gb1.x)*(gm1.x*inv) + bt1.x, 0.f) * em1.x;
    o1.y = fmaxf((acc1.y + gb1.y)*(gm1.y*inv) + bt1.y, 0.f) * em1.y;
    *(float2*)&d_g[(size_t)warp*DD + d0] = o0;
    *(float2*)&d_g[(size_t)warp*DD + d1] = o1;
}

// ---------------------------------------------------------------
// K6 (tf32 MMA, cp.async 3-stage): o1[b,d,h] = sum_n g[b,n,d]*w1[h,n]
// ---------------------------------------------------------------
__global__ void __launch_bounds__(256, 2) k_gemm1(const float* __restrict__ w1) {
    extern __shared__ unsigned smu[];
    int b = blockIdx.y, h0 = blockIdx.x * 128;
    int tid = threadIdx.x;
    int w = tid >> 5, lane = tid & 31;
    int g = lane >> 2, t4 = lane & 3;
    int wm = (w & 1) * 64, wn = (w >> 1) * 32;
    float c[4][4][4] = {};

    #define G1_LOAD(st, n0)                                                      \
        {                                                                        \
            unsigned* pA = smu + (st)*STG_KN;                                    \
            unsigned* pB = pA + A_KN_WORDS;                                      \
            _Pragma("unroll")                                                    \
            for (int a = 0; a < 4; a++) {                                        \
                int idx = tid + a*256;                                           \
                int kk = idx >> 5, d4 = idx & 31;                                \
                cpa16(pA + kk*136 + d4*4,                                        \
                      d_g + ((size_t)b*NN + (n0) + kk)*DD + d4*4);               \
            }                                                                    \
            _Pragma("unroll")                                                    \
            for (int a = 0; a < 4; a++) {                                        \
                int idx = tid + a*256;                                           \
                int hh = idx >> 3, k4 = idx & 7;                                 \
                cpa16(pB + hh*36 + k4*4, w1 + (h0 + hh)*NN + (n0) + k4*4);       \
            }                                                                    \
        }

    G1_LOAD(0, 0) CP_COMMIT;
    G1_LOAD(1, 32) CP_COMMIT;
    #pragma unroll 1
    for (int it = 0; it < NN/32; it++) {
        CP_WAIT1;
        __syncthreads();
        if (it + 2 < NN/32) { G1_LOAD((it+2)%NSTAGE, (it+2)*32) CP_COMMIT; }
        unsigned* pA = smu + (it%NSTAGE)*STG_KN;
        unsigned* pB = pA + A_KN_WORDS;
        CHUNK_KN(pA, pB)
    }
    #undef G1_LOAD
    #pragma unroll
    for (int mi = 0; mi < 4; mi++)
        #pragma unroll
        for (int ni = 0; ni < 4; ni++) {
            int row = wm + mi*16 + g, col = h0 + wn + ni*8 + t4*2;
            float2 v0 = {c[mi][ni][0], c[mi][ni][1]};
            float2 v1 = {c[mi][ni][2], c[mi][ni][3]};
            *(float2*)&d_o1[((size_t)b*DD + row    )*HIDN + col] = v0;
            *(float2*)&d_o1[((size_t)b*DD + row + 8)*HIDN + col] = v1;
        }
}

// ---------------------------------------------------------------
// K7 (tf32 MMA, cp.async 3-stage): out = sigmoid(o1 @ w2^T + b2)
// ---------------------------------------------------------------
__global__ void __launch_bounds__(256, 2) k_gemm2(const float* __restrict__ w2,
                                                  const float* __restrict__ b2,
                                                  float* __restrict__ out) {
    extern __shared__ unsigned smu[];
    int b = blockIdx.y, h20 = blockIdx.x * 128;
    int tid = threadIdx.x;
    int w = tid >> 5, lane = tid & 31;
    int g = lane >> 2, t4 = lane & 3;
    int wm = (w & 1) * 64, wn = (w >> 1) * 32;
    float c[4][4][4] = {};

    #define G2_LOAD(st, hk0)                                                     \
        {                                                                        \
            unsigned* pA = smu + (st)*STG_MK;                                    \
            unsigned* pB = pA + MK_WORDS;                                        \
            _Pragma("unroll")                                                    \
            for (int a = 0; a < 4; a++) {                                        \
                int idx = tid + a*256;                                           \
                int dd = idx >> 3, k4 = idx & 7;                                 \
                cpa16(pA + dd*36 + k4*4,                                         \
                      d_o1 + ((size_t)b*DD + dd)*HIDN + (hk0) + k4*4);           \
            }                                                                    \
            _Pragma("unroll")                                                    \
            for (int a = 0; a < 4; a++) {                                        \
                int idx = tid + a*256;                                           \
                int hh = idx >> 3, k4 = idx & 7;                                 \
                cpa16(pB + hh*36 + k4*4, w2 + (h20 + hh)*HIDN + (hk0) + k4*4);   \
            }                                                                    \
        }

    G2_LOAD(0, 0) CP_COMMIT;
    G2_LOAD(1, 32) CP_COMMIT;
    #pragma unroll 1
    for (int it = 0; it < HIDN/32; it++) {
        CP_WAIT1;
        __syncthreads();
        if (it + 2 < HIDN/32) { G2_LOAD((it+2)%NSTAGE, (it+2)*32) CP_COMMIT; }
        unsigned* pA = smu + (it%NSTAGE)*STG_MK;
        unsigned* pB = pA + MK_WORDS;
        CHUNK_MK(pA, pB)
    }
    #undef G2_LOAD
    #pragma unroll
    for (int mi = 0; mi < 4; mi++)
        #pragma unroll
        for (int ni = 0; ni < 4; ni++) {
            int row = wm + mi*16 + g, col = h20 + wn + ni*8 + t4*2;
            float bb0 = b2[col], bb1 = b2[col + 1];
            float2 v0, v1;
            v0.x = 1.0f/(1.0f + expf(-(c[mi][ni][0] + bb0)));
            v0.y = 1.0f/(1.0f + expf(-(c[mi][ni][1] + bb1)));
            v1.x = 1.0f/(1.0f + expf(-(c[mi][ni][2] + bb0)));
            v1.y = 1.0f/(1.0f + expf(-(c[mi][ni][3] + bb1)));
            *(float2*)&out[((size_t)b*DD + row    )*HIDN + col] = v0;
            *(float2*)&out[((size_t)b*DD + row + 8)*HIDN + col] = v1;
        }
}

// ---------------------------------------------------------------
// K8: pack trailing outputs (emb_weight copy, topk_idx as float)
// ---------------------------------------------------------------
__global__ void k_pack(const float* __restrict__ emb, float* __restrict__ out, int mode) {
    int i = blockIdx.x*256 + threadIdx.x;
    const int OUT0 = BB*DD*HIDN;
    if (i < NN*DD) out[OUT0 + i] = emb[i];
    if (mode && i < NN*KTOP) out[OUT0 + NN*DD + i] = (float)d_topk[i];
}

extern "C" void kernel_launch(void* const* d_in, const int* in_sizes, int n_in,
                              void* d_out, int out_size) {
    const float* data  = (const float*)d_in[0];
    const float* emb   = (const float*)d_in[1];
    const float* linw  = (const float*)d_in[2];
    const float* ai    = (const float*)d_in[3];
    const float* aj    = (const float*)d_in[4];
    const float* aei   = (const float*)d_in[5];
    const float* aej   = (const float*)d_in[6];
    const float* gbias = (const float*)d_in[7];
    const float* gamma = (const float*)d_in[8];
    const float* beta  = (const float*)d_in[9];
    const float* w1    = (const float*)d_in[10];
    const float* w2    = (const float*)d_in[11];
    const float* b2    = (const float*)d_in[12];
    float* out = (float*)d_out;

    static cudaStream_t s2 = nullptr;
    static cudaEvent_t evFork = nullptr, evJoin = nullptr;
    static bool attrs_done = false;
    const int smem_kn = NSTAGE*STG_KN*4;   // 107520 B
    const int smem_mk = NSTAGE*STG_MK*4;   // 110592 B
    if (!attrs_done) {
        cudaFuncSetAttribute(k_xl,    cudaFuncAttributeMaxDynamicSharedMemorySize, smem_kn);
        cudaFuncSetAttribute(k_gemm1, cudaFuncAttributeMaxDynamicSharedMemorySize, smem_kn);
        cudaFuncSetAttribute(k_gemm2, cudaFuncAttributeMaxDynamicSharedMemorySize, smem_mk);
        cudaStreamCreateWithFlags(&s2, cudaStreamNonBlocking);
        cudaEventCreateWithFlags(&evFork, cudaEventDisableTiming);
        cudaEventCreateWithFlags(&evJoin, cudaEventDisableTiming);
        attrs_done = true;
    }

    const int OUT0 = BB*DD*HIDN;
    int tail = (out_size >= OUT0 + NN*DD) ? 1 : 0;
    int mode = (out_size >= OUT0 + NN*DD + NN*KTOP) ? 1 : 0;

    // fork: side stream runs the emb-only chain concurrently with xl
    cudaEventRecord(evFork, 0);
    cudaStreamWaitEvent(s2, evFork, 0);

    k_norm<<<NN, 128, 0, s2>>>(emb, aei, aej);
    k_cos <<<dim3(8, 8), 256, 0, s2>>>(emb);
    k_topk<<<NN/8, 256, 0, s2>>>();
    if (tail) k_pack<<<(NN*DD + 255)/256, 256, 0, s2>>>(emb, out, mode);

    k_xl  <<<dim3(4, BB), 256, smem_kn>>>(data, linw);
    k_pq  <<<(BB*NN)/8, 256>>>(ai, aj);

    // join before attn (needs topk + norm outputs + pq)
    cudaEventRecord(evJoin, s2);
    cudaStreamWaitEvent(0, evJoin, 0);

    k_attn<<<(BB*NN)/8, 256>>>(emb, gbias, gamma, beta);
    k_gemm1<<<dim3(4, BB), 256, smem_kn>>>(w1);
    k_gemm2<<<dim3(4, BB), 256, smem_mk>>>(w2, b2, out);
}

// round 9
// speedup vs baseline: 3.6750x; 1.0132x over previous
#include <cuda_runtime.h>
#include <cuda_fp16.h>
#include <math.h>

#define BB   64
#define NN   512
#define FIN  256
#define DD   128
#define KTOP 20
#define HIDN 512

// ---- scratch (device globals; no allocations) ----
static __device__ __half d_xl16[BB*NN*DD];     // [b,n,d] lin(x), fp16
static __device__ __half d_gT16[BB*DD*NN];     // [b,d,n] gated GCN output (transposed), fp16
static __device__ __half d_o116[BB*DD*HIDN];   // [b,d,h] first linear, fp16
static __device__ __half d_w116[HIDN*NN];      // w1 fp16
static __device__ __half d_w216[HIDN*HIDN];    // w2 fp16
static __device__ float  d_p [BB*NN];
static __device__ float  d_q [BB*NN];
static __device__ float  d_rinv[NN];
static __device__ float  d_r [NN];
static __device__ float  d_s [NN];
static __device__ float  d_cosm[NN*NN];
static __device__ int    d_topk[NN*KTOP];

// ---------------- MMA / cp.async helpers ----------------
__device__ __forceinline__ void mma_tf32(float c[4],
        unsigned a0, unsigned a1, unsigned a2, unsigned a3,
        unsigned b0, unsigned b1) {
    asm volatile(
        "mma.sync.aligned.m16n8k8.row.col.f32.tf32.tf32.f32 "
        "{%0,%1,%2,%3}, {%4,%5,%6,%7}, {%8,%9}, {%0,%1,%2,%3};\n"
        : "+f"(c[0]), "+f"(c[1]), "+f"(c[2]), "+f"(c[3])
        : "r"(a0), "r"(a1), "r"(a2), "r"(a3), "r"(b0), "r"(b1));
}
__device__ __forceinline__ void mma_f16(float c[4],
        unsigned a0, unsigned a1, unsigned a2, unsigned a3,
        unsigned b0, unsigned b1) {
    asm volatile(
        "mma.sync.aligned.m16n8k16.row.col.f32.f16.f16.f32 "
        "{%0,%1,%2,%3}, {%4,%5,%6,%7}, {%8,%9}, {%0,%1,%2,%3};\n"
        : "+f"(c[0]), "+f"(c[1]), "+f"(c[2]), "+f"(c[3])
        : "r"(a0), "r"(a1), "r"(a2), "r"(a3), "r"(b0), "r"(b1));
}
__device__ __forceinline__ void cpa16(void* dst, const void* src) {
    unsigned ds = (unsigned)__cvta_generic_to_shared(dst);
    asm volatile("cp.async.cg.shared.global [%0], [%1], 16;" :: "r"(ds), "l"(src));
}
#define CP_COMMIT asm volatile("cp.async.commit_group;")
#define CP_WAIT1  asm volatile("cp.async.wait_group 1;")
#define CP_WAIT0  asm volatile("cp.async.wait_group 0;")
#define NSTAGE    3

// ---- tf32 k_xl geometry ----
#define A_KN_WORDS 4352          // [32 k][136]
#define B_KN_WORDS 4608          // [128][36]
#define STG_KN     (A_KN_WORDS + B_KN_WORDS)   // 8960 w

// ---- fp16 gemm geometry: K-chunk 64 halves; rows of 72 halves (36 words) ----
#define HROW_W     36
#define H_OP_WORDS (128*HROW_W)                 // 4608 words per operand
#define STG_H      (2*H_OP_WORDS)               // 9216 words per stage

// tf32 chunk: A [k][136], B [m][36]
#define CHUNK_KN(pA, pB)                                                        \
    _Pragma("unroll")                                                            \
    for (int ks = 0; ks < 4; ks++) {                                             \
        int k8 = ks*8;                                                           \
        unsigned af[4][4], bf[4][2];                                             \
        _Pragma("unroll")                                                        \
        for (int mi = 0; mi < 4; mi++) {                                         \
            int r = wm + mi*16 + g;                                              \
            af[mi][0] = (pA)[(k8+t4  )*136 + r    ];                             \
            af[mi][1] = (pA)[(k8+t4  )*136 + r + 8];                             \
            af[mi][2] = (pA)[(k8+t4+4)*136 + r    ];                             \
            af[mi][3] = (pA)[(k8+t4+4)*136 + r + 8];                             \
        }                                                                        \
        _Pragma("unroll")                                                        \
        for (int ni = 0; ni < 4; ni++) {                                         \
            int rn = wn + ni*8 + g;                                              \
            bf[ni][0] = (pB)[rn*36 + k8+t4    ];                                 \
            bf[ni][1] = (pB)[rn*36 + k8+t4 + 4];                                 \
        }                                                                        \
        _Pragma("unroll")                                                        \
        for (int mi = 0; mi < 4; mi++)                                           \
            _Pragma("unroll")                                                    \
            for (int ni = 0; ni < 4; ni++)                                       \
                mma_tf32(c[mi][ni], af[mi][0], af[mi][1], af[mi][2],             \
                         af[mi][3], bf[ni][0], bf[ni][1]);                       \
    }

// fp16 chunk (K=64): A [m][36w], B [n][36w]; 4 k-steps of 16
#define CHUNK_H(pA, pB)                                                         \
    _Pragma("unroll")                                                            \
    for (int ks = 0; ks < 4; ks++) {                                             \
        int kw = ks*8;                                                           \
        unsigned af[4][4], bf[4][2];                                             \
        _Pragma("unroll")                                                        \
        for (int mi = 0; mi < 4; mi++) {                                         \
            int r = wm + mi*16 + g;                                              \
            af[mi][0] = (pA)[(r    )*HROW_W + kw + t4    ];                      \
            af[mi][1] = (pA)[(r + 8)*HROW_W + kw + t4    ];                      \
            af[mi][2] = (pA)[(r    )*HROW_W + kw + t4 + 4];                      \
            af[mi][3] = (pA)[(r + 8)*HROW_W + kw + t4 + 4];                      \
        }                                                                        \
        _Pragma("unroll")                                                        \
        for (int ni = 0; ni < 4; ni++) {                                         \
            int rn = wn + ni*8 + g;                                              \
            bf[ni][0] = (pB)[rn*HROW_W + kw + t4    ];                           \
            bf[ni][1] = (pB)[rn*HROW_W + kw + t4 + 4];                           \
        }                                                                        \
        _Pragma("unroll")                                                        \
        for (int mi = 0; mi < 4; mi++)                                           \
            _Pragma("unroll")                                                    \
            for (int ni = 0; ni < 4; ni++)                                       \
                mma_f16(c[mi][ni], af[mi][0], af[mi][1], af[mi][2],              \
                        af[mi][3], bf[ni][0], bf[ni][1]);                        \
    }

// ---------------------------------------------------------------
// K0: per-node norms + emb dot att_em
// ---------------------------------------------------------------
__global__ void k_norm(const float* __restrict__ emb,
                       const float* __restrict__ aei,
                       const float* __restrict__ aej) {
    int n = blockIdx.x, t = threadIdx.x;
    float w  = emb[n*DD + t];
    float v0 = w*w, v1 = w*aei[t], v2 = w*aej[t];
    #pragma unroll
    for (int o = 16; o; o >>= 1) {
        v0 += __shfl_xor_sync(0xffffffffu, v0, o);
        v1 += __shfl_xor_sync(0xffffffffu, v1, o);
        v2 += __shfl_xor_sync(0xffffffffu, v2, o);
    }
    __shared__ float s0[4], s1[4], s2[4];
    int wid = t >> 5, lane = t & 31;
    if (lane == 0) { s0[wid]=v0; s1[wid]=v1; s2[wid]=v2; }
    __syncthreads();
    if (t == 0) {
        d_rinv[n] = rsqrtf(s0[0]+s0[1]+s0[2]+s0[3]);
        d_r[n] = s1[0]+s1[1]+s1[2]+s1[3];
        d_s[n] = s2[0]+s2[1]+s2[2]+s2[3];
    }
}

// ---------------------------------------------------------------
// K1: cosine matrix (fp32; must not perturb topk)
// ---------------------------------------------------------------
__global__ void k_cos(const float* __restrict__ emb) {
    __shared__ float sAt[32][68];
    __shared__ float sBt[32][68];
    int i0 = blockIdx.y * 64, j0 = blockIdx.x * 64;
    int tid = threadIdx.x;
    int tx = tid & 15, ty = tid >> 4;
    float c[4][4] = {};
    for (int k0 = 0; k0 < DD; k0 += 32) {
        #pragma unroll
        for (int a = 0; a < 8; a++) {
            int idx = tid + a*256;
            int row = idx >> 5, kk = idx & 31;
            sAt[kk][row] = emb[(i0+row)*DD + k0 + kk];
            sBt[kk][row] = emb[(j0+row)*DD + k0 + kk];
        }
        __syncthreads();
        #pragma unroll
        for (int kk = 0; kk < 32; kk++) {
            float av[4], bv[4];
            *(float4*)av = *(const float4*)&sAt[kk][ty*4];
            *(float4*)bv = *(const float4*)&sBt[kk][tx*4];
            #pragma unroll
            for (int ii = 0; ii < 4; ii++)
                #pragma unroll
                for (int jj = 0; jj < 4; jj++)
                    c[ii][jj] += av[ii]*bv[jj];
        }
        __syncthreads();
    }
    float rj[4];
    #pragma unroll
    for (int jj = 0; jj < 4; jj++) rj[jj] = d_rinv[j0 + tx*4 + jj];
    #pragma unroll
    for (int ii = 0; ii < 4; ii++) {
        float ri = d_rinv[i0 + ty*4 + ii];
        float4 v;
        v.x = c[ii][0]*ri*rj[0]; v.y = c[ii][1]*ri*rj[1];
        v.z = c[ii][2]*ri*rj[2]; v.w = c[ii][3]*ri*rj[3];
        *(float4*)&d_cosm[(i0 + ty*4 + ii)*NN + j0 + tx*4] = v;
    }
}

// ---------------------------------------------------------------
// K2: top-20 per row — one warp per row, registers only
// ---------------------------------------------------------------
__global__ void k_topk() {
    int row  = (blockIdx.x*256 + threadIdx.x) >> 5;
    int lane = threadIdx.x & 31;
    float v[16];
    #pragma unroll
    for (int j = 0; j < 16; j++) v[j] = d_cosm[row*NN + lane + 32*j];
    for (int t = 0; t < KTOP; t++) {
        float bv = v[0]; int bj = 0;
        #pragma unroll
        for (int j = 1; j < 16; j++)
            if (v[j] > bv) { bv = v[j]; bj = j; }
        int bidx = lane + 32*bj;
        #pragma unroll
        for (int o = 16; o; o >>= 1) {
            float ov = __shfl_xor_sync(0xffffffffu, bv, o);
            int   oi = __shfl_xor_sync(0xffffffffu, bidx, o);
            if (ov > bv || (ov == bv && oi < bidx)) { bv = ov; bidx = oi; }
        }
        if (lane == 0) d_topk[row*KTOP + t] = bidx;
        #pragma unroll
        for (int j = 0; j < 16; j++)
            if (lane + 32*j == bidx) v[j] = -INFINITY;
    }
}

// ---------------------------------------------------------------
// K_cvt: fp32 -> fp16 weight converts. The destination is a
// __device__ global referenced FROM DEVICE CODE (never passed from
// host — host-side decay of a __device__ symbol yields the host
// shadow address, which on GB300/ATS silently writes host memory).
// ---------------------------------------------------------------
__global__ void k_cvt_w1(const float* __restrict__ src) {
    int idx = blockIdx.x*256 + threadIdx.x;     // HIDN*NN/4 threads
    float4 v = *(const float4*)(src + idx*4);
    __half2* d2 = (__half2*)(d_w116 + idx*4);
    d2[0] = __floats2half2_rn(v.x, v.y);
    d2[1] = __floats2half2_rn(v.z, v.w);
}
__global__ void k_cvt_w2(const float* __restrict__ src) {
    int idx = blockIdx.x*256 + threadIdx.x;     // HIDN*HIDN/4 threads
    float4 v = *(const float4*)(src + idx*4);
    __half2* d2 = (__half2*)(d_w216 + idx*4);
    d2[0] = __floats2half2_rn(v.x, v.y);
    d2[1] = __floats2half2_rn(v.z, v.w);
}

// ---------------------------------------------------------------
// K3: xl (tf32 MMA, 3-stage) + fused p/q epilogue.
// ---------------------------------------------------------------
__global__ void __launch_bounds__(256, 2) k_xl(const float* __restrict__ data,
                                               const float* __restrict__ linw,
                                               const float* __restrict__ ai,
                                               const float* __restrict__ aj) {
    extern __shared__ unsigned smu[];
    __shared__ float spq[DD][2];
    int b = blockIdx.y, n0 = blockIdx.x * 128;
    int tid = threadIdx.x;
    int w = tid >> 5, lane = tid & 31;
    int g = lane >> 2, t4 = lane & 3;
    int wm = (w & 1) * 64, wn = (w >> 1) * 32;
    if (tid < DD) { spq[tid][0] = 0.f; spq[tid][1] = 0.f; }
    float c[4][4][4] = {};

    #define XL_LOAD(st, f0)                                                      \
        {                                                                        \
            unsigned* pA = smu + (st)*STG_KN;                                    \
            unsigned* pB = pA + A_KN_WORDS;                                      \
            _Pragma("unroll")                                                    \
            for (int a = 0; a < 4; a++) {                                        \
                int idx = tid + a*256;                                           \
                int kk = idx >> 5, n4 = idx & 31;                                \
                cpa16(pA + kk*136 + n4*4,                                        \
                      data + ((size_t)b*FIN + (f0) + kk)*NN + n0 + n4*4);        \
            }                                                                    \
            _Pragma("unroll")                                                    \
            for (int a = 0; a < 4; a++) {                                        \
                int idx = tid + a*256;                                           \
                int dd = idx >> 3, k4 = idx & 7;                                 \
                cpa16(pB + dd*36 + k4*4, linw + dd*FIN + (f0) + k4*4);           \
            }                                                                    \
        }

    XL_LOAD(0, 0) CP_COMMIT;
    XL_LOAD(1, 32) CP_COMMIT;
    #pragma unroll 1
    for (int it = 0; it < FIN/32; it++) {
        if (it + 1 < FIN/32) { CP_WAIT1; } else { CP_WAIT0; }
        __syncthreads();
        if (it + 2 < FIN/32) { XL_LOAD((it+2)%NSTAGE, (it+2)*32) CP_COMMIT; }
        unsigned* pA = smu + (it%NSTAGE)*STG_KN;
        unsigned* pB = pA + A_KN_WORDS;
        CHUNK_KN(pA, pB)
    }
    #undef XL_LOAD

    // epilogue: write xl16 + accumulate p/q partials
    float pv[8] = {}, qv[8] = {};
    #pragma unroll
    for (int mi = 0; mi < 4; mi++)
        #pragma unroll
        for (int ni = 0; ni < 4; ni++) {
            int row = n0 + wm + mi*16 + g, col = wn + ni*8 + t4*2;
            size_t i0 = ((size_t)b*NN + row    )*DD + col;
            size_t i1 = ((size_t)b*NN + row + 8)*DD + col;
            *(__half2*)&d_xl16[i0] = __floats2half2_rn(c[mi][ni][0], c[mi][ni][1]);
            *(__half2*)&d_xl16[i1] = __floats2half2_rn(c[mi][ni][2], c[mi][ni][3]);
            float a0 = ai[col], a1 = ai[col+1];
            float j0 = aj[col], j1 = aj[col+1];
            pv[mi*2  ] += c[mi][ni][0]*a0 + c[mi][ni][1]*a1;
            pv[mi*2+1] += c[mi][ni][2]*a0 + c[mi][ni][3]*a1;
            qv[mi*2  ] += c[mi][ni][0]*j0 + c[mi][ni][1]*j1;
            qv[mi*2+1] += c[mi][ni][2]*j0 + c[mi][ni][3]*j1;
        }
    #pragma unroll
    for (int r = 0; r < 8; r++) {
        pv[r] += __shfl_xor_sync(0xffffffffu, pv[r], 1);
        pv[r] += __shfl_xor_sync(0xffffffffu, pv[r], 2);
        qv[r] += __shfl_xor_sync(0xffffffffu, qv[r], 1);
        qv[r] += __shfl_xor_sync(0xffffffffu, qv[r], 2);
    }
    if (t4 == 0) {
        #pragma unroll
        for (int mi = 0; mi < 4; mi++) {
            int r0 = wm + mi*16 + g;
            atomicAdd(&spq[r0][0],   pv[mi*2]);
            atomicAdd(&spq[r0][1],   qv[mi*2]);
            atomicAdd(&spq[r0+8][0], pv[mi*2+1]);
            atomicAdd(&spq[r0+8][1], qv[mi*2+1]);
        }
    }
    __syncthreads();
    if (tid < 2*DD) {
        int row = tid >> 1, which = tid & 1;
        float v = spq[row][which];
        if (which == 0) d_p[b*NN + n0 + row] = v;
        else            d_q[b*NN + n0 + row] = v;
    }
}

// ---------------------------------------------------------------
// K5: attention softmax + aggregate (fp16 gather from L2) +
//     BN + ReLU + emb gate, emit gT[b][d][n] fp16 via smem staging.
// ---------------------------------------------------------------
#define GTS_PITCH 264
__global__ void __launch_bounds__(256, 1) k_attn2(const float* __restrict__ emb,
                                                  const float* __restrict__ gbias,
                                                  const float* __restrict__ gamma,
                                                  const float* __restrict__ beta) {
    extern __shared__ __half gts[];    // [128][GTS_PITCH] = 67584 B
    int b = blockIdx.x >> 1, nhalf = blockIdx.x & 1;
    int n0 = nhalf * 256;
    int tid = threadIdx.x, wrp = tid >> 5, lane = tid & 31;

    const float inv = rsqrtf(1.0f + 1e-5f);
    for (int i = 0; i < 32; i++) {
        int n = n0 + wrp*32 + i;
        int widx = b*NN + n;
        int src_k = 0; float alpha = -1e30f;
        if (lane < KTOP) {
            src_k = d_topk[n*KTOP + lane];
            alpha = d_p[widx] + d_r[n] + d_q[b*NN + src_k] + d_s[src_k];
            alpha = alpha > 0.f ? alpha : 0.2f*alpha;
        }
        float m = alpha;
        #pragma unroll
        for (int o = 16; o; o >>= 1) m = fmaxf(m, __shfl_xor_sync(0xffffffffu, m, o));
        float ex = (lane < KTOP) ? expf(alpha - m) : 0.f;
        float sm = ex;
        #pragma unroll
        for (int o = 16; o; o >>= 1) sm += __shfl_xor_sync(0xffffffffu, sm, o);
        float aw = ex / sm;

        float2 acc0 = {0.f,0.f}, acc1 = {0.f,0.f};
        #pragma unroll
        for (int k = 0; k < KTOP; k++) {
            int   sk = __shfl_sync(0xffffffffu, src_k, k);
            float ak = __shfl_sync(0xffffffffu, aw,  k);
            const __half2* xr = (const __half2*)(d_xl16 + ((size_t)b*NN + sk)*DD);
            float2 f0 = __half22float2(xr[lane]);
            float2 f1 = __half22float2(xr[lane + 32]);
            acc0.x += ak*f0.x; acc0.y += ak*f0.y;
            acc1.x += ak*f1.x; acc1.y += ak*f1.y;
        }
        int d0 = 2*lane, d1 = 2*lane + 64;
        float h0 = fmaxf((acc0.x + gbias[d0  ])*(gamma[d0  ]*inv) + beta[d0  ], 0.f) * emb[n*DD + d0];
        float h1 = fmaxf((acc0.y + gbias[d0+1])*(gamma[d0+1]*inv) + beta[d0+1], 0.f) * emb[n*DD + d0+1];
        float h2 = fmaxf((acc1.x + gbias[d1  ])*(gamma[d1  ]*inv) + beta[d1  ], 0.f) * emb[n*DD + d1];
        float h3 = fmaxf((acc1.y + gbias[d1+1])*(gamma[d1+1]*inv) + beta[d1+1], 0.f) * emb[n*DD + d1+1];
        int nn = n - n0;
        gts[(d0  )*GTS_PITCH + nn] = __float2half(h0);
        gts[(d0+1)*GTS_PITCH + nn] = __float2half(h1);
        gts[(d1  )*GTS_PITCH + nn] = __float2half(h2);
        gts[(d1+1)*GTS_PITCH + nn] = __float2half(h3);
    }
    __syncthreads();
    // writeout of the FULL gT tile: 128 rows x 256 halves
    for (int row = wrp; row < DD; row += 8) {
        *(uint4*)(d_gT16 + ((size_t)b*DD + row)*NN + n0 + lane*8) =
            *(uint4*)(gts + row*GTS_PITCH + lane*8);
    }
}

// ---------------------------------------------------------------
// K6 (fp16 MMA): o1[b,d,h] = sum_n gT[b,d,n] * w1[h,n]
// ---------------------------------------------------------------
__global__ void __launch_bounds__(256, 2) k_gemm1() {
    extern __shared__ unsigned smu[];
    int b = blockIdx.y, h0 = blockIdx.x * 128;
    int tid = threadIdx.x;
    int w = tid >> 5, lane = tid & 31;
    int g = lane >> 2, t4 = lane & 3;
    int wm = (w & 1) * 64, wn = (w >> 1) * 32;
    float c[4][4][4] = {};

    #define G1_LOAD(st, k0)                                                      \
        {                                                                        \
            unsigned* pA = smu + (st)*STG_H;                                     \
            unsigned* pB = pA + H_OP_WORDS;                                      \
            _Pragma("unroll")                                                    \
            for (int a = 0; a < 4; a++) {                                        \
                int idx = tid + a*256;                                           \
                int row = idx >> 3, seg = idx & 7;                               \
                cpa16(pA + row*HROW_W + seg*4,                                   \
                      d_gT16 + ((size_t)b*DD + row)*NN + (k0) + seg*8);          \
            }                                                                    \
            _Pragma("unroll")                                                    \
            for (int a = 0; a < 4; a++) {                                        \
                int idx = tid + a*256;                                           \
                int row = idx >> 3, seg = idx & 7;                               \
                cpa16(pB + row*HROW_W + seg*4,                                   \
                      d_w116 + (size_t)(h0 + row)*NN + (k0) + seg*8);            \
            }                                                                    \
        }

    G1_LOAD(0, 0) CP_COMMIT;
    G1_LOAD(1, 64) CP_COMMIT;
    #pragma unroll 1
    for (int it = 0; it < NN/64; it++) {
        if (it + 1 < NN/64) { CP_WAIT1; } else { CP_WAIT0; }
        __syncthreads();
        if (it + 2 < NN/64) { G1_LOAD((it+2)%NSTAGE, (it+2)*64) CP_COMMIT; }
        unsigned* pA = smu + (it%NSTAGE)*STG_H;
        unsigned* pB = pA + H_OP_WORDS;
        CHUNK_H(pA, pB)
    }
    #undef G1_LOAD
    #pragma unroll
    for (int mi = 0; mi < 4; mi++)
        #pragma unroll
        for (int ni = 0; ni < 4; ni++) {
            int row = wm + mi*16 + g, col = h0 + wn + ni*8 + t4*2;
            *(__half2*)&d_o116[((size_t)b*DD + row    )*HIDN + col] =
                __floats2half2_rn(c[mi][ni][0], c[mi][ni][1]);
            *(__half2*)&d_o116[((size_t)b*DD + row + 8)*HIDN + col] =
                __floats2half2_rn(c[mi][ni][2], c[mi][ni][3]);
        }
}

// ---------------------------------------------------------------
// K7 (fp16 MMA): out[b,d,h2] = sigmoid(sum_h o1[b,d,h]*w2[h2,h] + b2)
// ---------------------------------------------------------------
__global__ void __launch_bounds__(256, 2) k_gemm2(const float* __restrict__ b2,
                                                  float* __restrict__ out) {
    extern __shared__ unsigned smu[];
    int b = blockIdx.y, h20 = blockIdx.x * 128;
    int tid = threadIdx.x;
    int w = tid >> 5, lane = tid & 31;
    int g = lane >> 2, t4 = lane & 3;
    int wm = (w & 1) * 64, wn = (w >> 1) * 32;
    float c[4][4][4] = {};

    #define G2_LOAD(st, k0)                                                      \
        {                                                                        \
            unsigned* pA = smu + (st)*STG_H;                                     \
            unsigned* pB = pA + H_OP_WORDS;                                      \
            _Pragma("unroll")                                                    \
            for (int a = 0; a < 4; a++) {                                        \
                int idx = tid + a*256;                                           \
                int row = idx >> 3, seg = idx & 7;                               \
                cpa16(pA + row*HROW_W + seg*4,                                   \
                      d_o116 + ((size_t)b*DD + row)*HIDN + (k0) + seg*8);        \
            }                                                                    \
            _Pragma("unroll")                                                    \
            for (int a = 0; a < 4; a++) {                                        \
                int idx = tid + a*256;                                           \
                int row = idx >> 3, seg = idx & 7;                               \
                cpa16(pB + row*HROW_W + seg*4,                                   \
                      d_w216 + (size_t)(h20 + row)*HIDN + (k0) + seg*8);         \
            }                                                                    \
        }

    G2_LOAD(0, 0) CP_COMMIT;
    G2_LOAD(1, 64) CP_COMMIT;
    #pragma unroll 1
    for (int it = 0; it < HIDN/64; it++) {
        if (it + 1 < HIDN/64) { CP_WAIT1; } else { CP_WAIT0; }
        __syncthreads();
        if (it + 2 < HIDN/64) { G2_LOAD((it+2)%NSTAGE, (it+2)*64) CP_COMMIT; }
        unsigned* pA = smu + (it%NSTAGE)*STG_H;
        unsigned* pB = pA + H_OP_WORDS;
        CHUNK_H(pA, pB)
    }
    #undef G2_LOAD
    #pragma unroll
    for (int mi = 0; mi < 4; mi++)
        #pragma unroll
        for (int ni = 0; ni < 4; ni++) {
            int row = wm + mi*16 + g, col = h20 + wn + ni*8 + t4*2;
            float bb0 = b2[col], bb1 = b2[col + 1];
            float2 v0, v1;
            v0.x = 1.0f/(1.0f + expf(-(c[mi][ni][0] + bb0)));
            v0.y = 1.0f/(1.0f + expf(-(c[mi][ni][1] + bb1)));
            v1.x = 1.0f/(1.0f + expf(-(c[mi][ni][2] + bb0)));
            v1.y = 1.0f/(1.0f + expf(-(c[mi][ni][3] + bb1)));
            *(float2*)&out[((size_t)b*DD + row    )*HIDN + col] = v0;
            *(float2*)&out[((size_t)b*DD + row + 8)*HIDN + col] = v1;
        }
}

// ---------------------------------------------------------------
// K8: pack trailing outputs (emb_weight copy, topk_idx as float)
// ---------------------------------------------------------------
__global__ void k_pack(const float* __restrict__ emb, float* __restrict__ out, int mode) {
    int i = blockIdx.x*256 + threadIdx.x;
    const int OUT0 = BB*DD*HIDN;
    if (i < NN*DD) out[OUT0 + i] = emb[i];
    if (mode && i < NN*KTOP) out[OUT0 + NN*DD + i] = (float)d_topk[i];
}

extern "C" void kernel_launch(void* const* d_in, const int* in_sizes, int n_in,
                              void* d_out, int out_size) {
    const float* data  = (const float*)d_in[0];
    const float* emb   = (const float*)d_in[1];
    const float* linw  = (const float*)d_in[2];
    const float* ai    = (const float*)d_in[3];
    const float* aj    = (const float*)d_in[4];
    const float* aei   = (const float*)d_in[5];
    const float* aej   = (const float*)d_in[6];
    const float* gbias = (const float*)d_in[7];
    const float* gamma = (const float*)d_in[8];
    const float* beta  = (const float*)d_in[9];
    const float* w1    = (const float*)d_in[10];
    const float* w2    = (const float*)d_in[11];
    const float* b2    = (const float*)d_in[12];
    float* out = (float*)d_out;

    static cudaStream_t s2 = nullptr;
    static cudaEvent_t evFork = nullptr, evJoin = nullptr;
    static bool init_done = false;
    const int smem_kn   = NSTAGE*STG_KN*4;   // 107520 B
    const int smem_h    = NSTAGE*STG_H*4;    // 110592 B
    const int smem_attn = DD*GTS_PITCH*2;    // 67584 B
    if (!init_done) {
        cudaFuncSetAttribute(k_xl,    cudaFuncAttributeMaxDynamicSharedMemorySize, smem_kn);
        cudaFuncSetAttribute(k_gemm1, cudaFuncAttributeMaxDynamicSharedMemorySize, smem_h);
        cudaFuncSetAttribute(k_gemm2, cudaFuncAttributeMaxDynamicSharedMemorySize, smem_h);
        cudaFuncSetAttribute(k_attn2, cudaFuncAttributeMaxDynamicSharedMemorySize, smem_attn);
        cudaStreamCreateWithFlags(&s2, cudaStreamNonBlocking);
        cudaEventCreateWithFlags(&evFork, cudaEventDisableTiming);
        cudaEventCreateWithFlags(&evJoin, cudaEventDisableTiming);
        init_done = true;
    }

    const int OUT0 = BB*DD*HIDN;
    int tail = (out_size >= OUT0 + NN*DD) ? 1 : 0;
    int mode = (out_size >= OUT0 + NN*DD + NN*KTOP) ? 1 : 0;

    // fork: side stream runs emb-only chain + weight converts concurrently with xl
    cudaEventRecord(evFork, 0);
    cudaStreamWaitEvent(s2, evFork, 0);

    k_cvt_w1<<<HIDN*NN/1024,   256, 0, s2>>>(w1);
    k_cvt_w2<<<HIDN*HIDN/1024, 256, 0, s2>>>(w2);
    k_norm<<<NN, 128, 0, s2>>>(emb, aei, aej);
    k_cos <<<dim3(8, 8), 256, 0, s2>>>(emb);
    k_topk<<<NN/8, 256, 0, s2>>>();
    if (tail) k_pack<<<(NN*DD + 255)/256, 256, 0, s2>>>(emb, out, mode);

    k_xl<<<dim3(4, BB), 256, smem_kn>>>(data, linw, ai, aj);

    // join: attn needs topk/norm; gemm1 needs w116
    cudaEventRecord(evJoin, s2);
    cudaStreamWaitEvent(0, evJoin, 0);

    k_attn2<<<2*BB, 256, smem_attn>>>(emb, gbias, gamma, beta);
    k_gemm1<<<dim3(4, BB), 256, smem_h>>>();
    k_gemm2<<<dim3(4, BB), 256, smem_h>>>(b2, out);
}